// round 1
// baseline (speedup 1.0000x reference)
#include <cuda_runtime.h>
#include <math.h>

// Problem constants
#define Bb  512
#define P1c 64
#define Lc  512
#define Hc  2048
#define Mc  (Bb * P1c)   // 32768 rows

// ---------------- scratch (no cudaMalloc allowed) ----------------
__device__ float g_mu1[Bb];
__device__ float g_rstd1[Bb];
__device__ float g_mu2[Bb];
__device__ float g_rstd2[Bb];
__device__ float g_C[Lc * Lc];                      // circulant filter, 1 MB
__device__ float g_y[(size_t)Mc * Lc];              // filtered signal, 64 MB
__device__ float g_z[(size_t)Mc * Hc];              // FFN hidden, 256 MB

// ---------------- f32x2 helpers (packed dual-fp32 FMA) ----------------
__device__ __forceinline__ unsigned long long pack_dup(float a) {
    unsigned long long r;
    unsigned int ai = __float_as_uint(a);
    asm("mov.b64 %0, {%1, %1};" : "=l"(r) : "r"(ai));
    return r;
}
__device__ __forceinline__ void fma2(unsigned long long &acc,
                                     unsigned long long a,
                                     unsigned long long b) {
    asm("fma.rn.f32x2 %0, %1, %2, %0;" : "+l"(acc) : "l"(a), "l"(b));
}
__device__ __forceinline__ float2 unpack2(unsigned long long v) {
    unsigned int lo, hi;
    asm("mov.b64 {%0, %1}, %2;" : "=r"(lo), "=r"(hi) : "l"(v));
    float2 f;
    f.x = __uint_as_float(lo);
    f.y = __uint_as_float(hi);
    return f;
}

// ---------------- per-batch mean / rstd over (P1, L) = 32768 elems ----------------
__global__ void batch_stats(const float* __restrict__ x,
                            float* __restrict__ mu,
                            float* __restrict__ rstd) {
    const int NPER = P1c * Lc;  // 32768
    const int b = blockIdx.x;
    const float4* xb = reinterpret_cast<const float4*>(x) + (size_t)b * (NPER / 4);
    float s = 0.f, ss = 0.f;
    for (int i = threadIdx.x; i < NPER / 4; i += blockDim.x) {
        float4 v = xb[i];
        s  += (v.x + v.y) + (v.z + v.w);
        ss += v.x * v.x + v.y * v.y + v.z * v.z + v.w * v.w;
    }
    __shared__ float sh_s[32], sh_ss[32];
    const int lane = threadIdx.x & 31, wid = threadIdx.x >> 5;
    for (int o = 16; o > 0; o >>= 1) {
        s  += __shfl_xor_sync(0xFFFFFFFFu, s,  o);
        ss += __shfl_xor_sync(0xFFFFFFFFu, ss, o);
    }
    if (lane == 0) { sh_s[wid] = s; sh_ss[wid] = ss; }
    __syncthreads();
    if (wid == 0) {
        const int nw = blockDim.x >> 5;
        s  = (lane < nw) ? sh_s[lane]  : 0.f;
        ss = (lane < nw) ? sh_ss[lane] : 0.f;
        for (int o = 16; o > 0; o >>= 1) {
            s  += __shfl_xor_sync(0xFFFFFFFFu, s,  o);
            ss += __shfl_xor_sync(0xFFFFFFFFu, ss, o);
        }
        if (lane == 0) {
            float m = s / NPER;
            float var = ss / NPER - m * m;
            mu[b] = m;
            rstd[b] = rsqrtf(var + 1e-5f);
        }
    }
}

// ---------------- build circulant C[m][n] = w[(n-m) mod L] / sqrt(L) ----------------
__global__ void build_C(const float* __restrict__ w, float* __restrict__ C) {
    const int n = blockIdx.x * blockDim.x + threadIdx.x;
    const int m = blockIdx.y;
    const float RSQRT_L = 0.04419417382415922f;  // 1/sqrt(512)
    C[m * Lc + n] = w[(n - m) & (Lc - 1)] * RSQRT_L;
}

// ---------------- SGEMM: D = epi( lnA(A) @ B )  ----------------
// 128x128 block tile, BK=16, 256 threads, 8x8 per thread, f32x2 accumulation.
// LN:   if true, apply (a - mu[b])*rstd[b]*g[p,l] + bb[p,l] to A elements on load
//       (A must have K == Lc == 512 in that case; row = b*64 + p).
// EPI:  0 = plain store, 1 = relu(acc + bias[n]), 2 = acc + bias[n] + res[row,n]
template <bool LN, int EPI>
__global__ void __launch_bounds__(256)
sgemm_kernel(const float* __restrict__ A, const float* __restrict__ Bg,
             float* __restrict__ D, const int K, const int N,
             const float* __restrict__ mu, const float* __restrict__ rstd,
             const float* __restrict__ lng, const float* __restrict__ lnb,
             const float* __restrict__ bias, const float* __restrict__ res) {
    __shared__ float As[2][16][132];   // transposed A tile, padded
    __shared__ float Bs[2][16][128];

    const int tid = threadIdx.x;
    const int tx = tid & 15;          // n direction
    const int ty = tid >> 4;          // m direction
    const int m0 = blockIdx.y * 128;
    const int n0 = blockIdx.x * 128;

    // A loader: 2 x float4 per thread, rows ar, ar+64; cols ac..ac+3
    const int ar = tid >> 2;
    const int ac = (tid & 3) << 2;
    // B loader: 2 x float4 per thread, rows br, br+8; cols bc..bc+3
    const int br = tid >> 5;
    const int bc = (tid & 31) << 2;

    const int nkt = K >> 4;

    unsigned long long acc[8][4];
#pragma unroll
    for (int i = 0; i < 8; i++)
#pragma unroll
        for (int j = 0; j < 4; j++) acc[i][j] = 0ull;

    float4 av[2], gv[2], lv[2], bv[2];
    float mub[2], rsb[2];

    auto fetch = [&](int kt) {
#pragma unroll
        for (int u = 0; u < 2; u++) {
            const int grow = m0 + ar + u * 64;
            const int gcol = (kt << 4) + ac;
            av[u] = *reinterpret_cast<const float4*>(&A[(size_t)grow * K + gcol]);
            if (LN) {
                const int bi = grow >> 6;
                const int p  = grow & 63;
                mub[u] = mu[bi];
                rsb[u] = rstd[bi];
                gv[u] = *reinterpret_cast<const float4*>(&lng[p * Lc + gcol]);
                lv[u] = *reinterpret_cast<const float4*>(&lnb[p * Lc + gcol]);
            }
            bv[u] = *reinterpret_cast<const float4*>(
                &Bg[(size_t)((kt << 4) + br + u * 8) * N + n0 + bc]);
        }
    };
    auto stash = [&](int s) {
#pragma unroll
        for (int u = 0; u < 2; u++) {
            float4 v = av[u];
            if (LN) {
                v.x = (v.x - mub[u]) * rsb[u] * gv[u].x + lv[u].x;
                v.y = (v.y - mub[u]) * rsb[u] * gv[u].y + lv[u].y;
                v.z = (v.z - mub[u]) * rsb[u] * gv[u].z + lv[u].z;
                v.w = (v.w - mub[u]) * rsb[u] * gv[u].w + lv[u].w;
            }
            const int row = ar + u * 64;
            As[s][ac + 0][row] = v.x;
            As[s][ac + 1][row] = v.y;
            As[s][ac + 2][row] = v.z;
            As[s][ac + 3][row] = v.w;
            *reinterpret_cast<float4*>(&Bs[s][br + u * 8][bc]) = bv[u];
        }
    };

    fetch(0);
    stash(0);
    __syncthreads();

    for (int kt = 0; kt < nkt; kt++) {
        const int s = kt & 1;
        if (kt + 1 < nkt) fetch(kt + 1);
#pragma unroll
        for (int k = 0; k < 16; k++) {
            const float4 a0 = *reinterpret_cast<const float4*>(&As[s][k][ty * 8]);
            const float4 a1 = *reinterpret_cast<const float4*>(&As[s][k][ty * 8 + 4]);
            const ulonglong2 q0 = *reinterpret_cast<const ulonglong2*>(&Bs[s][k][tx * 8]);
            const ulonglong2 q1 = *reinterpret_cast<const ulonglong2*>(&Bs[s][k][tx * 8 + 4]);
            unsigned long long ap[8];
            ap[0] = pack_dup(a0.x); ap[1] = pack_dup(a0.y);
            ap[2] = pack_dup(a0.z); ap[3] = pack_dup(a0.w);
            ap[4] = pack_dup(a1.x); ap[5] = pack_dup(a1.y);
            ap[6] = pack_dup(a1.z); ap[7] = pack_dup(a1.w);
            unsigned long long bp[4];
            bp[0] = q0.x; bp[1] = q0.y; bp[2] = q1.x; bp[3] = q1.y;
#pragma unroll
            for (int i = 0; i < 8; i++)
#pragma unroll
                for (int j = 0; j < 4; j++) fma2(acc[i][j], ap[i], bp[j]);
        }
        if (kt + 1 < nkt) stash(s ^ 1);
        __syncthreads();
    }

    // epilogue
#pragma unroll
    for (int i = 0; i < 8; i++) {
        const int row = m0 + ty * 8 + i;
#pragma unroll
        for (int h = 0; h < 2; h++) {
            float2 p0 = unpack2(acc[i][2 * h]);
            float2 p1 = unpack2(acc[i][2 * h + 1]);
            float4 v = make_float4(p0.x, p0.y, p1.x, p1.y);
            const int col = n0 + tx * 8 + h * 4;
            if (EPI == 1) {
                const float4 bq = *reinterpret_cast<const float4*>(&bias[col]);
                v.x = fmaxf(v.x + bq.x, 0.f);
                v.y = fmaxf(v.y + bq.y, 0.f);
                v.z = fmaxf(v.z + bq.z, 0.f);
                v.w = fmaxf(v.w + bq.w, 0.f);
            } else if (EPI == 2) {
                const float4 bq = *reinterpret_cast<const float4*>(&bias[col]);
                const float4 rq =
                    *reinterpret_cast<const float4*>(&res[(size_t)row * N + col]);
                v.x += bq.x + rq.x;
                v.y += bq.y + rq.y;
                v.z += bq.z + rq.z;
                v.w += bq.w + rq.w;
            }
            *reinterpret_cast<float4*>(&D[(size_t)row * N + col]) = v;
        }
    }
}

// ---------------- launcher ----------------
extern "C" void kernel_launch(void* const* d_in, const int* in_sizes, int n_in,
                              void* d_out, int out_size) {
    const float* x    = (const float*)d_in[0];
    const float* w    = (const float*)d_in[1];
    const float* ln1w = (const float*)d_in[2];
    const float* ln1b = (const float*)d_in[3];
    const float* ln2w = (const float*)d_in[4];
    const float* ln2b = (const float*)d_in[5];
    const float* w1   = (const float*)d_in[6];
    const float* b1   = (const float*)d_in[7];
    const float* w2   = (const float*)d_in[8];
    const float* b2   = (const float*)d_in[9];
    float* out = (float*)d_out;

    float *mu1, *rstd1, *mu2, *rstd2, *C, *y, *z;
    cudaGetSymbolAddress((void**)&mu1,   g_mu1);
    cudaGetSymbolAddress((void**)&rstd1, g_rstd1);
    cudaGetSymbolAddress((void**)&mu2,   g_mu2);
    cudaGetSymbolAddress((void**)&rstd2, g_rstd2);
    cudaGetSymbolAddress((void**)&C,     g_C);
    cudaGetSymbolAddress((void**)&y,     g_y);
    cudaGetSymbolAddress((void**)&z,     g_z);

    // 1) per-batch stats of x (for LN1)
    batch_stats<<<Bb, 256>>>(x, mu1, rstd1);
    // 2) circulant filter matrix from w
    build_C<<<dim3(Lc / 256, Lc), 256>>>(w, C);
    // 3) y = LN1(x) @ C       (freq_filter as GEMM), M=32768, K=512, N=512
    sgemm_kernel<true, 0><<<dim3(Lc / 128, Mc / 128), 256>>>(
        x, C, y, Lc, Lc, mu1, rstd1, ln1w, ln1b, nullptr, nullptr);
    // 4) per-batch stats of y (for LN2)
    batch_stats<<<Bb, 256>>>(y, mu2, rstd2);
    // 5) z = relu(LN2(y) @ w1 + b1), M=32768, K=512, N=2048
    sgemm_kernel<true, 1><<<dim3(Hc / 128, Mc / 128), 256>>>(
        y, w1, z, Lc, Hc, mu2, rstd2, ln2w, ln2b, b1, nullptr);
    // 6) out = z @ w2 + b2 + x,      M=32768, K=2048, N=512
    sgemm_kernel<false, 2><<<dim3(Lc / 128, Mc / 128), 256>>>(
        z, w2, out, Hc, Lc, nullptr, nullptr, nullptr, nullptr, b2, x);
}

// round 3
// speedup vs baseline: 2.2361x; 2.2361x over previous
#include <cuda_runtime.h>
#include <cuda_bf16.h>
#include <math.h>
#include <stdint.h>

#define Bb  512
#define P1c 64
#define Lc  512
#define Hc  2048
#define Mc  (Bb * P1c)   // 32768 rows

// ---------------- scratch ----------------
__device__ float g_mu1[Bb];
__device__ float g_rstd1[Bb];
__device__ float g_mu2[Bb];
__device__ float g_rstd2[Bb];
__device__ float g_y[(size_t)Mc * Lc];                       // 64 MB fp32
__device__ __nv_bfloat16 g_a1h[(size_t)Mc * Lc];
__device__ __nv_bfloat16 g_a1l[(size_t)Mc * Lc];
__device__ __nv_bfloat16 g_a2h[(size_t)Mc * Lc];
__device__ __nv_bfloat16 g_a2l[(size_t)Mc * Lc];
__device__ __nv_bfloat16 g_cth[Lc * Lc];                     // C^T [N,K]
__device__ __nv_bfloat16 g_ctl[Lc * Lc];
__device__ __nv_bfloat16 g_w1th[(size_t)Hc * Lc];            // w1^T [2048,512]
__device__ __nv_bfloat16 g_w1tl[(size_t)Hc * Lc];
__device__ __nv_bfloat16 g_w2th[(size_t)Lc * Hc];            // w2^T [512,2048]
__device__ __nv_bfloat16 g_w2tl[(size_t)Lc * Hc];
__device__ __nv_bfloat16 g_zh[(size_t)Mc * Hc];              // 128 MB
__device__ __nv_bfloat16 g_zl[(size_t)Mc * Hc];

// ---------------- helpers ----------------
__device__ __forceinline__ uint32_t smem_u32(const void* p) {
    uint32_t a;
    asm("{ .reg .u64 t; cvta.to.shared.u64 t, %1; cvt.u32.u64 %0, t; }" : "=r"(a) : "l"(p));
    return a;
}
__device__ __forceinline__ void split_bf(float v, unsigned short& h, unsigned short& l) {
    __nv_bfloat16 hb = __float2bfloat16(v);
    float rem = v - __bfloat162float(hb);
    __nv_bfloat16 lb = __float2bfloat16(rem);
    h = __bfloat16_as_ushort(hb);
    l = __bfloat16_as_ushort(lb);
}
__device__ __forceinline__ void cp16(uint32_t dst, const void* src) {
    asm volatile("cp.async.cg.shared.global [%0], [%1], 16;"
                 :: "r"(dst), "l"((unsigned long long)__cvta_generic_to_global(src)));
}
__device__ __forceinline__ void ldm4(uint32_t addr, uint32_t* r) {
    asm volatile("ldmatrix.sync.aligned.m8n8.x4.shared.b16 {%0,%1,%2,%3}, [%4];"
                 : "=r"(r[0]), "=r"(r[1]), "=r"(r[2]), "=r"(r[3]) : "r"(addr));
}
__device__ __forceinline__ void mma16816(float* c, const uint32_t* a,
                                         uint32_t b0, uint32_t b1) {
    asm volatile(
        "mma.sync.aligned.m16n8k16.row.col.f32.bf16.bf16.f32 "
        "{%0,%1,%2,%3}, {%4,%5,%6,%7}, {%8,%9}, {%0,%1,%2,%3};"
        : "+f"(c[0]), "+f"(c[1]), "+f"(c[2]), "+f"(c[3])
        : "r"(a[0]), "r"(a[1]), "r"(a[2]), "r"(a[3]), "r"(b0), "r"(b1));
}

// ---------------- per-batch mean / rstd over (P1, L) ----------------
__global__ void batch_stats(const float* __restrict__ x,
                            float* __restrict__ mu, float* __restrict__ rstd) {
    const int NPER = P1c * Lc;
    const int b = blockIdx.x;
    const float4* xb = reinterpret_cast<const float4*>(x) + (size_t)b * (NPER / 4);
    float s = 0.f, ss = 0.f;
    for (int i = threadIdx.x; i < NPER / 4; i += blockDim.x) {
        float4 v = xb[i];
        s  += (v.x + v.y) + (v.z + v.w);
        ss += v.x * v.x + v.y * v.y + v.z * v.z + v.w * v.w;
    }
    __shared__ float sh_s[32], sh_ss[32];
    const int lane = threadIdx.x & 31, wid = threadIdx.x >> 5;
    for (int o = 16; o > 0; o >>= 1) {
        s  += __shfl_xor_sync(0xFFFFFFFFu, s,  o);
        ss += __shfl_xor_sync(0xFFFFFFFFu, ss, o);
    }
    if (lane == 0) { sh_s[wid] = s; sh_ss[wid] = ss; }
    __syncthreads();
    if (wid == 0) {
        const int nw = blockDim.x >> 5;
        s  = (lane < nw) ? sh_s[lane]  : 0.f;
        ss = (lane < nw) ? sh_ss[lane] : 0.f;
        for (int o = 16; o > 0; o >>= 1) {
            s  += __shfl_xor_sync(0xFFFFFFFFu, s,  o);
            ss += __shfl_xor_sync(0xFFFFFFFFu, ss, o);
        }
        if (lane == 0) {
            float m = s / NPER;
            float var = ss / NPER - m * m;
            mu[b] = m;
            rstd[b] = rsqrtf(var + 1e-5f);
        }
    }
}

// ---------------- LN + bf16 hi/lo split ----------------
__global__ void ln_split(const float* __restrict__ x,
                         const float* __restrict__ mu, const float* __restrict__ rstd,
                         const float* __restrict__ g, const float* __restrict__ bb,
                         __nv_bfloat16* __restrict__ hi, __nv_bfloat16* __restrict__ lo) {
    size_t idx = (size_t)blockIdx.x * blockDim.x + threadIdx.x;
    int row = (int)(idx >> 7);
    int c4  = (int)(idx & 127) << 2;
    int b = row >> 6, p = row & 63;
    float m = mu[b], r = rstd[b];
    float4 v  = *(const float4*)&x[(size_t)row * Lc + c4];
    float4 gv = *(const float4*)&g[p * Lc + c4];
    float4 bv = *(const float4*)&bb[p * Lc + c4];
    float o0 = (v.x - m) * r * gv.x + bv.x;
    float o1 = (v.y - m) * r * gv.y + bv.y;
    float o2 = (v.z - m) * r * gv.z + bv.z;
    float o3 = (v.w - m) * r * gv.w + bv.w;
    ushort4 h4, l4;
    split_bf(o0, h4.x, l4.x); split_bf(o1, h4.y, l4.y);
    split_bf(o2, h4.z, l4.z); split_bf(o3, h4.w, l4.w);
    *(ushort4*)&hi[(size_t)row * Lc + c4] = h4;
    *(ushort4*)&lo[(size_t)row * Lc + c4] = l4;
}

// ---------------- Ct[n][k] = w[(n-k)&511]/sqrt(L), split ----------------
__global__ void build_ct(const float* __restrict__ w,
                         __nv_bfloat16* __restrict__ hi, __nv_bfloat16* __restrict__ lo) {
    int k = blockIdx.x * blockDim.x + threadIdx.x;
    int n = blockIdx.y;
    float v = w[(n - k) & (Lc - 1)] * 0.04419417382415922f;
    unsigned short h, l;
    split_bf(v, h, l);
    hi[n * Lc + k] = __ushort_as_bfloat16(h);
    lo[n * Lc + k] = __ushort_as_bfloat16(l);
}

// ---------------- transpose + split: [K,N] fp32 -> [N,K] bf16 hi/lo ----------------
__global__ void transpose_split(const float* __restrict__ in,
                                __nv_bfloat16* __restrict__ hi, __nv_bfloat16* __restrict__ lo,
                                int K, int N) {
    __shared__ float t[32][33];
    int n0 = blockIdx.x * 32, k0 = blockIdx.y * 32;
    int tx = threadIdx.x, ty = threadIdx.y;
    for (int i = ty; i < 32; i += 8)
        t[i][tx] = in[(size_t)(k0 + i) * N + n0 + tx];
    __syncthreads();
    for (int i = ty; i < 32; i += 8) {
        float v = t[tx][i];
        size_t o = (size_t)(n0 + i) * K + k0 + tx;
        unsigned short h, l;
        split_bf(v, h, l);
        hi[o] = __ushort_as_bfloat16(h);
        lo[o] = __ushort_as_bfloat16(l);
    }
}

// ---------------- HMMA split-bf16 GEMM ----------------
// CTA tile 128x128, BK=32, 8 warps (4 in M x 2 in N), warp tile 32x64.
// A [M,K] bf16 hi/lo (k-contig), B [N,K] bf16 hi/lo (k-contig).
// Accumulate Ahi*Bhi + Ahi*Blo + Alo*Bhi in fp32.
// EPI 0: Dout=acc; 1: relu(acc+bias) -> Zhi/Zlo split; 2: Dout=acc+bias+res.
#define RSTRIDE 80                      // 64B data + 16B pad per k-row
#define MTILE_B (128 * RSTRIDE)         // 10240 per matrix
#define STG     (4 * MTILE_B)           // Ahi,Alo,Bhi,Blo = 40960
#define NSTAGE  4
#define DSMEM   (NSTAGE * STG)          // 163840

template <int EPI>
__global__ void __launch_bounds__(256, 1)
hmma_gemm(const __nv_bfloat16* __restrict__ Ahi, const __nv_bfloat16* __restrict__ Alo,
          const __nv_bfloat16* __restrict__ Bhi, const __nv_bfloat16* __restrict__ Blo,
          float* __restrict__ Dout,
          __nv_bfloat16* __restrict__ Zhi, __nv_bfloat16* __restrict__ Zlo,
          const float* __restrict__ bias, const float* __restrict__ res,
          int K, int N) {
    extern __shared__ char smem[];
    const uint32_t sb = smem_u32(smem);
    const int tid = threadIdx.x, wid = tid >> 5, lane = tid & 31;
    const int wy = wid & 3, wx = wid >> 2;            // 4 M-warps x 2 N-warps
    const int m0 = blockIdx.y * 128, n0 = blockIdx.x * 128;

    // per-lane ldmatrix address offsets (within a k16 sub-tile)
    const uint32_t offA = (uint32_t)((wy * 32 + (lane & 7) + ((lane >> 3) & 1) * 8) * RSTRIDE
                                     + (lane >> 4) * 16);
    const uint32_t offB = (uint32_t)((wx * 64 + (lane & 7) + (lane >> 4) * 8) * RSTRIDE
                                     + ((lane >> 3) & 1) * 16);

    auto load_stage = [&](int s, int kt) {
        const uint32_t ab = sb + s * STG;
#pragma unroll
        for (int i = 0; i < 2; i++) {
            const int j = tid + (i << 8);       // 0..511
            const int row = j >> 2, c = j & 3;
            const uint32_t off = row * RSTRIDE + c * 16;
            const size_t asrc = (size_t)(m0 + row) * K + (size_t)kt * 32 + c * 8;
            const size_t bsrc = (size_t)(n0 + row) * K + (size_t)kt * 32 + c * 8;
            cp16(ab + off,               Ahi + asrc);
            cp16(ab + MTILE_B + off,     Alo + asrc);
            cp16(ab + 2 * MTILE_B + off, Bhi + bsrc);
            cp16(ab + 3 * MTILE_B + off, Blo + bsrc);
        }
        asm volatile("cp.async.commit_group;");
    };

    float acc[2][8][4];
#pragma unroll
    for (int mi = 0; mi < 2; mi++)
#pragma unroll
        for (int ni = 0; ni < 8; ni++)
#pragma unroll
            for (int q = 0; q < 4; q++) acc[mi][ni][q] = 0.f;

    const int nkt = K >> 5;
    const int npre = nkt < 3 ? nkt : 3;
    for (int s = 0; s < npre; s++) load_stage(s, s);

    for (int kt = 0; kt < nkt; kt++) {
        if (kt + 3 < nkt) load_stage((kt + 3) & 3, kt + 3);
        const int rem = nkt - 1 - kt;
        if (rem >= 3)      asm volatile("cp.async.wait_group 3;" ::: "memory");
        else if (rem == 2) asm volatile("cp.async.wait_group 2;" ::: "memory");
        else if (rem == 1) asm volatile("cp.async.wait_group 1;" ::: "memory");
        else               asm volatile("cp.async.wait_group 0;" ::: "memory");
        __syncthreads();

        const uint32_t st = sb + (kt & 3) * STG;
#pragma unroll
        for (int kk = 0; kk < 2; kk++) {
            uint32_t ah[2][4], al[2][4], bh[4][4], bl[4][4];
#pragma unroll
            for (int mi = 0; mi < 2; mi++) {
                const uint32_t a = st + offA + mi * (16 * RSTRIDE) + kk * 32;
                ldm4(a, ah[mi]);
                ldm4(a + MTILE_B, al[mi]);
            }
#pragma unroll
            for (int nf = 0; nf < 4; nf++) {
                const uint32_t b = st + 2 * MTILE_B + offB + nf * (16 * RSTRIDE) + kk * 32;
                ldm4(b, bh[nf]);
                ldm4(b + MTILE_B, bl[nf]);
            }
#pragma unroll
            for (int mi = 0; mi < 2; mi++)
#pragma unroll
                for (int nf = 0; nf < 4; nf++) {
                    mma16816(acc[mi][nf * 2 + 0], ah[mi], bh[nf][0], bh[nf][1]);
                    mma16816(acc[mi][nf * 2 + 1], ah[mi], bh[nf][2], bh[nf][3]);
                    mma16816(acc[mi][nf * 2 + 0], ah[mi], bl[nf][0], bl[nf][1]);
                    mma16816(acc[mi][nf * 2 + 1], ah[mi], bl[nf][2], bl[nf][3]);
                    mma16816(acc[mi][nf * 2 + 0], al[mi], bh[nf][0], bh[nf][1]);
                    mma16816(acc[mi][nf * 2 + 1], al[mi], bh[nf][2], bh[nf][3]);
                }
        }
        __syncthreads();
    }

    // ---- epilogue ----
    const int r0 = m0 + wy * 32 + (lane >> 2);
    const int cbase = n0 + wx * 64 + (lane & 3) * 2;
#pragma unroll
    for (int mi = 0; mi < 2; mi++) {
#pragma unroll
        for (int ni = 0; ni < 8; ni++) {
            const int col = cbase + ni * 8;
            const int ra = r0 + mi * 16;
            const int rb = ra + 8;
            float* c = acc[mi][ni];
            if (EPI == 0) {
                *(float2*)&Dout[(size_t)ra * N + col] = make_float2(c[0], c[1]);
                *(float2*)&Dout[(size_t)rb * N + col] = make_float2(c[2], c[3]);
            } else if (EPI == 1) {
                const float2 bq = *(const float2*)&bias[col];
                float v0 = fmaxf(c[0] + bq.x, 0.f), v1 = fmaxf(c[1] + bq.y, 0.f);
                float v2 = fmaxf(c[2] + bq.x, 0.f), v3 = fmaxf(c[3] + bq.y, 0.f);
                ushort2 h0, l0, h1, l1;
                split_bf(v0, h0.x, l0.x); split_bf(v1, h0.y, l0.y);
                split_bf(v2, h1.x, l1.x); split_bf(v3, h1.y, l1.y);
                *(ushort2*)&Zhi[(size_t)ra * N + col] = h0;
                *(ushort2*)&Zlo[(size_t)ra * N + col] = l0;
                *(ushort2*)&Zhi[(size_t)rb * N + col] = h1;
                *(ushort2*)&Zlo[(size_t)rb * N + col] = l1;
            } else {
                const float2 bq = *(const float2*)&bias[col];
                const float2 q0 = *(const float2*)&res[(size_t)ra * N + col];
                const float2 q1 = *(const float2*)&res[(size_t)rb * N + col];
                *(float2*)&Dout[(size_t)ra * N + col] =
                    make_float2(c[0] + bq.x + q0.x, c[1] + bq.y + q0.y);
                *(float2*)&Dout[(size_t)rb * N + col] =
                    make_float2(c[2] + bq.x + q1.x, c[3] + bq.y + q1.y);
            }
        }
    }
}

// ---------------- launcher ----------------
extern "C" void kernel_launch(void* const* d_in, const int* in_sizes, int n_in,
                              void* d_out, int out_size) {
    const float* x    = (const float*)d_in[0];
    const float* w    = (const float*)d_in[1];
    const float* ln1w = (const float*)d_in[2];
    const float* ln1b = (const float*)d_in[3];
    const float* ln2w = (const float*)d_in[4];
    const float* ln2b = (const float*)d_in[5];
    const float* w1   = (const float*)d_in[6];
    const float* b1   = (const float*)d_in[7];
    const float* w2   = (const float*)d_in[8];
    const float* b2   = (const float*)d_in[9];
    float* out = (float*)d_out;

    float *mu1, *rstd1, *mu2, *rstd2, *y;
    __nv_bfloat16 *a1h, *a1l, *a2h, *a2l, *cth, *ctl, *w1th, *w1tl, *w2th, *w2tl, *zh, *zl;
    cudaGetSymbolAddress((void**)&mu1,   g_mu1);
    cudaGetSymbolAddress((void**)&rstd1, g_rstd1);
    cudaGetSymbolAddress((void**)&mu2,   g_mu2);
    cudaGetSymbolAddress((void**)&rstd2, g_rstd2);
    cudaGetSymbolAddress((void**)&y,     g_y);
    cudaGetSymbolAddress((void**)&a1h,   g_a1h);
    cudaGetSymbolAddress((void**)&a1l,   g_a1l);
    cudaGetSymbolAddress((void**)&a2h,   g_a2h);
    cudaGetSymbolAddress((void**)&a2l,   g_a2l);
    cudaGetSymbolAddress((void**)&cth,   g_cth);
    cudaGetSymbolAddress((void**)&ctl,   g_ctl);
    cudaGetSymbolAddress((void**)&w1th,  g_w1th);
    cudaGetSymbolAddress((void**)&w1tl,  g_w1tl);
    cudaGetSymbolAddress((void**)&w2th,  g_w2th);
    cudaGetSymbolAddress((void**)&w2tl,  g_w2tl);
    cudaGetSymbolAddress((void**)&zh,    g_zh);
    cudaGetSymbolAddress((void**)&zl,    g_zl);

    cudaFuncSetAttribute(hmma_gemm<0>, cudaFuncAttributeMaxDynamicSharedMemorySize, DSMEM);
    cudaFuncSetAttribute(hmma_gemm<1>, cudaFuncAttributeMaxDynamicSharedMemorySize, DSMEM);
    cudaFuncSetAttribute(hmma_gemm<2>, cudaFuncAttributeMaxDynamicSharedMemorySize, DSMEM);

    // 1) LN1 stats + split
    batch_stats<<<Bb, 256>>>(x, mu1, rstd1);
    ln_split<<<(Mc * Lc / 4) / 256, 256>>>(x, mu1, rstd1, ln1w, ln1b, a1h, a1l);
    // 2) operand prep
    build_ct<<<dim3(2, Lc), 256>>>(w, cth, ctl);
    transpose_split<<<dim3(Hc / 32, Lc / 32), dim3(32, 8)>>>(w1, w1th, w1tl, Lc, Hc);
    transpose_split<<<dim3(Lc / 32, Hc / 32), dim3(32, 8)>>>(w2, w2th, w2tl, Hc, Lc);
    // 3) y = LN1(x) @ C        M=32768 K=512 N=512
    hmma_gemm<0><<<dim3(Lc / 128, Mc / 128), 256, DSMEM>>>(
        a1h, a1l, cth, ctl, y, nullptr, nullptr, nullptr, nullptr, Lc, Lc);
    // 4) LN2 stats + split
    batch_stats<<<Bb, 256>>>(y, mu2, rstd2);
    ln_split<<<(Mc * Lc / 4) / 256, 256>>>(y, mu2, rstd2, ln2w, ln2b, a2h, a2l);
    // 5) z = relu(LN2(y) @ w1 + b1)   M=32768 K=512 N=2048, split-bf16 out
    hmma_gemm<1><<<dim3(Hc / 128, Mc / 128), 256, DSMEM>>>(
        a2h, a2l, w1th, w1tl, nullptr, zh, zl, b1, nullptr, Lc, Hc);
    // 6) out = z @ w2 + b2 + x        M=32768 K=2048 N=512
    hmma_gemm<2><<<dim3(Lc / 128, Mc / 128), 256, DSMEM>>>(
        zh, zl, w2th, w2tl, out, nullptr, nullptr, b2, x, Hc, Lc);
}

// round 4
// speedup vs baseline: 2.7729x; 1.2401x over previous
#include <cuda_runtime.h>
#include <cuda_bf16.h>
#include <math.h>
#include <stdint.h>

#define Bb  512
#define P1c 64
#define Lc  512
#define Hc  2048
#define Mc  (Bb * P1c)   // 32768 rows

// ---------------- scratch ----------------
__device__ float g_mu1[Bb];
__device__ float g_rstd1[Bb];
__device__ float g_mu2[Bb];
__device__ float g_rstd2[Bb];
__device__ float g_y[(size_t)Mc * Lc];                       // 64 MB fp32
__device__ __nv_bfloat16 g_a1h[(size_t)Mc * Lc];
__device__ __nv_bfloat16 g_a1l[(size_t)Mc * Lc];
__device__ __nv_bfloat16 g_a2h[(size_t)Mc * Lc];
__device__ __nv_bfloat16 g_a2l[(size_t)Mc * Lc];
__device__ __nv_bfloat16 g_cth[Lc * Lc];                     // C^T [N,K]
__device__ __nv_bfloat16 g_ctl[Lc * Lc];
__device__ __nv_bfloat16 g_w1th[(size_t)Hc * Lc];            // w1^T [2048,512]
__device__ __nv_bfloat16 g_w1tl[(size_t)Hc * Lc];
__device__ __nv_bfloat16 g_w2th[(size_t)Lc * Hc];            // w2^T [512,2048]
__device__ __nv_bfloat16 g_w2tl[(size_t)Lc * Hc];
__device__ __nv_bfloat16 g_zh[(size_t)Mc * Hc];              // 128 MB
__device__ __nv_bfloat16 g_zl[(size_t)Mc * Hc];

// ---------------- helpers ----------------
__device__ __forceinline__ uint32_t smem_u32(const void* p) {
    uint32_t a;
    asm("{ .reg .u64 t; cvta.to.shared.u64 t, %1; cvt.u32.u64 %0, t; }" : "=r"(a) : "l"(p));
    return a;
}
__device__ __forceinline__ void split_bf(float v, unsigned short& h, unsigned short& l) {
    __nv_bfloat16 hb = __float2bfloat16(v);
    float rem = v - __bfloat162float(hb);
    __nv_bfloat16 lb = __float2bfloat16(rem);
    h = __bfloat16_as_ushort(hb);
    l = __bfloat16_as_ushort(lb);
}
__device__ __forceinline__ void cp16(uint32_t dst, const void* src) {
    asm volatile("cp.async.cg.shared.global [%0], [%1], 16;"
                 :: "r"(dst), "l"((unsigned long long)__cvta_generic_to_global(src)));
}
__device__ __forceinline__ void ldm4(uint32_t addr, uint32_t* r) {
    asm volatile("ldmatrix.sync.aligned.m8n8.x4.shared.b16 {%0,%1,%2,%3}, [%4];"
                 : "=r"(r[0]), "=r"(r[1]), "=r"(r[2]), "=r"(r[3]) : "r"(addr));
}
__device__ __forceinline__ void mma16816(float* c, const uint32_t* a,
                                         uint32_t b0, uint32_t b1) {
    asm volatile(
        "mma.sync.aligned.m16n8k16.row.col.f32.bf16.bf16.f32 "
        "{%0,%1,%2,%3}, {%4,%5,%6,%7}, {%8,%9}, {%0,%1,%2,%3};"
        : "+f"(c[0]), "+f"(c[1]), "+f"(c[2]), "+f"(c[3])
        : "r"(a[0]), "r"(a[1]), "r"(a[2]), "r"(a[3]), "r"(b0), "r"(b1));
}

// ---------------- per-batch mean / rstd over (P1, L) ----------------
__global__ void batch_stats(const float* __restrict__ x,
                            float* __restrict__ mu, float* __restrict__ rstd) {
    const int NPER = P1c * Lc;
    const int b = blockIdx.x;
    const float4* xb = reinterpret_cast<const float4*>(x) + (size_t)b * (NPER / 4);
    float s = 0.f, ss = 0.f;
    for (int i = threadIdx.x; i < NPER / 4; i += blockDim.x) {
        float4 v = xb[i];
        s  += (v.x + v.y) + (v.z + v.w);
        ss += v.x * v.x + v.y * v.y + v.z * v.z + v.w * v.w;
    }
    __shared__ float sh_s[32], sh_ss[32];
    const int lane = threadIdx.x & 31, wid = threadIdx.x >> 5;
    for (int o = 16; o > 0; o >>= 1) {
        s  += __shfl_xor_sync(0xFFFFFFFFu, s,  o);
        ss += __shfl_xor_sync(0xFFFFFFFFu, ss, o);
    }
    if (lane == 0) { sh_s[wid] = s; sh_ss[wid] = ss; }
    __syncthreads();
    if (wid == 0) {
        const int nw = blockDim.x >> 5;
        s  = (lane < nw) ? sh_s[lane]  : 0.f;
        ss = (lane < nw) ? sh_ss[lane] : 0.f;
        for (int o = 16; o > 0; o >>= 1) {
            s  += __shfl_xor_sync(0xFFFFFFFFu, s,  o);
            ss += __shfl_xor_sync(0xFFFFFFFFu, ss, o);
        }
        if (lane == 0) {
            float m = s / NPER;
            float var = ss / NPER - m * m;
            mu[b] = m;
            rstd[b] = rsqrtf(var + 1e-5f);
        }
    }
}

// ---------------- LN + bf16 hi/lo split ----------------
__global__ void ln_split(const float* __restrict__ x,
                         const float* __restrict__ mu, const float* __restrict__ rstd,
                         const float* __restrict__ g, const float* __restrict__ bb,
                         __nv_bfloat16* __restrict__ hi, __nv_bfloat16* __restrict__ lo) {
    size_t idx = (size_t)blockIdx.x * blockDim.x + threadIdx.x;
    int row = (int)(idx >> 7);
    int c4  = (int)(idx & 127) << 2;
    int b = row >> 6, p = row & 63;
    float m = mu[b], r = rstd[b];
    float4 v  = *(const float4*)&x[(size_t)row * Lc + c4];
    float4 gv = *(const float4*)&g[p * Lc + c4];
    float4 bv = *(const float4*)&bb[p * Lc + c4];
    float o0 = (v.x - m) * r * gv.x + bv.x;
    float o1 = (v.y - m) * r * gv.y + bv.y;
    float o2 = (v.z - m) * r * gv.z + bv.z;
    float o3 = (v.w - m) * r * gv.w + bv.w;
    ushort4 h4, l4;
    split_bf(o0, h4.x, l4.x); split_bf(o1, h4.y, l4.y);
    split_bf(o2, h4.z, l4.z); split_bf(o3, h4.w, l4.w);
    *(ushort4*)&hi[(size_t)row * Lc + c4] = h4;
    *(ushort4*)&lo[(size_t)row * Lc + c4] = l4;
}

// ---------------- Ct[n][k] = w[(n-k)&511]/sqrt(L), split ----------------
__global__ void build_ct(const float* __restrict__ w,
                         __nv_bfloat16* __restrict__ hi, __nv_bfloat16* __restrict__ lo) {
    int k = blockIdx.x * blockDim.x + threadIdx.x;
    int n = blockIdx.y;
    float v = w[(n - k) & (Lc - 1)] * 0.04419417382415922f;
    unsigned short h, l;
    split_bf(v, h, l);
    hi[n * Lc + k] = __ushort_as_bfloat16(h);
    lo[n * Lc + k] = __ushort_as_bfloat16(l);
}

// ---------------- transpose + split: [K,N] fp32 -> [N,K] bf16 hi/lo ----------------
__global__ void transpose_split(const float* __restrict__ in,
                                __nv_bfloat16* __restrict__ hi, __nv_bfloat16* __restrict__ lo,
                                int K, int N) {
    __shared__ float t[32][33];
    int n0 = blockIdx.x * 32, k0 = blockIdx.y * 32;
    int tx = threadIdx.x, ty = threadIdx.y;
    for (int i = ty; i < 32; i += 8)
        t[i][tx] = in[(size_t)(k0 + i) * N + n0 + tx];
    __syncthreads();
    for (int i = ty; i < 32; i += 8) {
        float v = t[tx][i];
        size_t o = (size_t)(n0 + i) * K + k0 + tx;
        unsigned short h, l;
        split_bf(v, h, l);
        hi[o] = __ushort_as_bfloat16(h);
        lo[o] = __ushort_as_bfloat16(l);
    }
}

// ---------------- HMMA split-bf16 GEMM ----------------
// CTA tile 128x128, BK=32, 8 warps (4M x 2N), warp tile 32x64.
// 2-stage pipeline, 2 CTAs/SM, single __syncthreads per k-tile.
// Accumulate Ahi*Bhi + Ahi*Blo + Alo*Bhi in fp32.
// EPI 0: Dout=acc; 1: relu(acc+bias) -> Zhi/Zlo split; 2: Dout=acc+bias+res.
#define RSTRIDE 80                      // 64B data + 16B pad per k-row
#define MTILE_B (128 * RSTRIDE)         // 10240 per matrix
#define STG     (4 * MTILE_B)           // Ahi,Alo,Bhi,Blo = 40960
#define DSMEM   (2 * STG)               // 81920

template <int EPI>
__global__ void __launch_bounds__(256, 2)
hmma_gemm(const __nv_bfloat16* __restrict__ Ahi, const __nv_bfloat16* __restrict__ Alo,
          const __nv_bfloat16* __restrict__ Bhi, const __nv_bfloat16* __restrict__ Blo,
          float* __restrict__ Dout,
          __nv_bfloat16* __restrict__ Zhi, __nv_bfloat16* __restrict__ Zlo,
          const float* __restrict__ bias, const float* __restrict__ res,
          int K, int N) {
    extern __shared__ char smem[];
    const uint32_t sb = smem_u32(smem);
    const int tid = threadIdx.x, wid = tid >> 5, lane = tid & 31;
    const int wy = wid & 3, wx = wid >> 2;            // 4 M-warps x 2 N-warps
    const int m0 = blockIdx.y * 128, n0 = blockIdx.x * 128;

    const uint32_t offA = (uint32_t)((wy * 32 + (lane & 7) + ((lane >> 3) & 1) * 8) * RSTRIDE
                                     + (lane >> 4) * 16);
    const uint32_t offB = (uint32_t)((wx * 64 + (lane & 7) + (lane >> 4) * 8) * RSTRIDE
                                     + ((lane >> 3) & 1) * 16);

    auto load_stage = [&](int s, int kt) {
        const uint32_t ab = sb + s * STG;
#pragma unroll
        for (int i = 0; i < 2; i++) {
            const int j = tid + (i << 8);       // 0..511
            const int row = j >> 2, c = j & 3;
            const uint32_t off = row * RSTRIDE + c * 16;
            const size_t asrc = (size_t)(m0 + row) * K + (size_t)kt * 32 + c * 8;
            const size_t bsrc = (size_t)(n0 + row) * K + (size_t)kt * 32 + c * 8;
            cp16(ab + off,               Ahi + asrc);
            cp16(ab + MTILE_B + off,     Alo + asrc);
            cp16(ab + 2 * MTILE_B + off, Bhi + bsrc);
            cp16(ab + 3 * MTILE_B + off, Blo + bsrc);
        }
        asm volatile("cp.async.commit_group;");
    };

    float acc[2][8][4];
#pragma unroll
    for (int mi = 0; mi < 2; mi++)
#pragma unroll
        for (int ni = 0; ni < 8; ni++)
#pragma unroll
            for (int q = 0; q < 4; q++) acc[mi][ni][q] = 0.f;

    const int nkt = K >> 5;
    load_stage(0, 0);

    for (int kt = 0; kt < nkt; kt++) {
        asm volatile("cp.async.wait_group 0;" ::: "memory");
        __syncthreads();
        if (kt + 1 < nkt) load_stage((kt + 1) & 1, kt + 1);

        const uint32_t st = sb + (kt & 1) * STG;
#pragma unroll
        for (int kk = 0; kk < 2; kk++) {
            uint32_t ah[2][4], al[2][4];
#pragma unroll
            for (int mi = 0; mi < 2; mi++) {
                const uint32_t a = st + offA + mi * (16 * RSTRIDE) + kk * 32;
                ldm4(a, ah[mi]);
                ldm4(a + MTILE_B, al[mi]);
            }
#pragma unroll
            for (int half = 0; half < 2; half++) {
                uint32_t bh[2][4], bl[2][4];
#pragma unroll
                for (int n2 = 0; n2 < 2; n2++) {
                    const uint32_t b = st + 2 * MTILE_B + offB
                                       + (half * 2 + n2) * (16 * RSTRIDE) + kk * 32;
                    ldm4(b, bh[n2]);
                    ldm4(b + MTILE_B, bl[n2]);
                }
#pragma unroll
                for (int mi = 0; mi < 2; mi++)
#pragma unroll
                    for (int n2 = 0; n2 < 2; n2++) {
                        const int nf = half * 2 + n2;
                        mma16816(acc[mi][nf * 2 + 0], ah[mi], bh[n2][0], bh[n2][1]);
                        mma16816(acc[mi][nf * 2 + 1], ah[mi], bh[n2][2], bh[n2][3]);
                        mma16816(acc[mi][nf * 2 + 0], ah[mi], bl[n2][0], bl[n2][1]);
                        mma16816(acc[mi][nf * 2 + 1], ah[mi], bl[n2][2], bl[n2][3]);
                        mma16816(acc[mi][nf * 2 + 0], al[mi], bh[n2][0], bh[n2][1]);
                        mma16816(acc[mi][nf * 2 + 1], al[mi], bh[n2][2], bh[n2][3]);
                    }
            }
        }
    }

    // ---- epilogue ----
    const int r0 = m0 + wy * 32 + (lane >> 2);
    const int cbase = n0 + wx * 64 + (lane & 3) * 2;
#pragma unroll
    for (int mi = 0; mi < 2; mi++) {
#pragma unroll
        for (int ni = 0; ni < 8; ni++) {
            const int col = cbase + ni * 8;
            const int ra = r0 + mi * 16;
            const int rb = ra + 8;
            float* c = acc[mi][ni];
            if (EPI == 0) {
                *(float2*)&Dout[(size_t)ra * N + col] = make_float2(c[0], c[1]);
                *(float2*)&Dout[(size_t)rb * N + col] = make_float2(c[2], c[3]);
            } else if (EPI == 1) {
                const float2 bq = *(const float2*)&bias[col];
                float v0 = fmaxf(c[0] + bq.x, 0.f), v1 = fmaxf(c[1] + bq.y, 0.f);
                float v2 = fmaxf(c[2] + bq.x, 0.f), v3 = fmaxf(c[3] + bq.y, 0.f);
                ushort2 h0, l0, h1, l1;
                split_bf(v0, h0.x, l0.x); split_bf(v1, h0.y, l0.y);
                split_bf(v2, h1.x, l1.x); split_bf(v3, h1.y, l1.y);
                *(ushort2*)&Zhi[(size_t)ra * N + col] = h0;
                *(ushort2*)&Zlo[(size_t)ra * N + col] = l0;
                *(ushort2*)&Zhi[(size_t)rb * N + col] = h1;
                *(ushort2*)&Zlo[(size_t)rb * N + col] = l1;
            } else {
                const float2 bq = *(const float2*)&bias[col];
                const float2 q0 = *(const float2*)&res[(size_t)ra * N + col];
                const float2 q1 = *(const float2*)&res[(size_t)rb * N + col];
                *(float2*)&Dout[(size_t)ra * N + col] =
                    make_float2(c[0] + bq.x + q0.x, c[1] + bq.y + q0.y);
                *(float2*)&Dout[(size_t)rb * N + col] =
                    make_float2(c[2] + bq.x + q1.x, c[3] + bq.y + q1.y);
            }
        }
    }
}

// ---------------- launcher ----------------
extern "C" void kernel_launch(void* const* d_in, const int* in_sizes, int n_in,
                              void* d_out, int out_size) {
    const float* x    = (const float*)d_in[0];
    const float* w    = (const float*)d_in[1];
    const float* ln1w = (const float*)d_in[2];
    const float* ln1b = (const float*)d_in[3];
    const float* ln2w = (const float*)d_in[4];
    const float* ln2b = (const float*)d_in[5];
    const float* w1   = (const float*)d_in[6];
    const float* b1   = (const float*)d_in[7];
    const float* w2   = (const float*)d_in[8];
    const float* b2   = (const float*)d_in[9];
    float* out = (float*)d_out;

    float *mu1, *rstd1, *mu2, *rstd2, *y;
    __nv_bfloat16 *a1h, *a1l, *a2h, *a2l, *cth, *ctl, *w1th, *w1tl, *w2th, *w2tl, *zh, *zl;
    cudaGetSymbolAddress((void**)&mu1,   g_mu1);
    cudaGetSymbolAddress((void**)&rstd1, g_rstd1);
    cudaGetSymbolAddress((void**)&mu2,   g_mu2);
    cudaGetSymbolAddress((void**)&rstd2, g_rstd2);
    cudaGetSymbolAddress((void**)&y,     g_y);
    cudaGetSymbolAddress((void**)&a1h,   g_a1h);
    cudaGetSymbolAddress((void**)&a1l,   g_a1l);
    cudaGetSymbolAddress((void**)&a2h,   g_a2h);
    cudaGetSymbolAddress((void**)&a2l,   g_a2l);
    cudaGetSymbolAddress((void**)&cth,   g_cth);
    cudaGetSymbolAddress((void**)&ctl,   g_ctl);
    cudaGetSymbolAddress((void**)&w1th,  g_w1th);
    cudaGetSymbolAddress((void**)&w1tl,  g_w1tl);
    cudaGetSymbolAddress((void**)&w2th,  g_w2th);
    cudaGetSymbolAddress((void**)&w2tl,  g_w2tl);
    cudaGetSymbolAddress((void**)&zh,    g_zh);
    cudaGetSymbolAddress((void**)&zl,    g_zl);

    cudaFuncSetAttribute(hmma_gemm<0>, cudaFuncAttributeMaxDynamicSharedMemorySize, DSMEM);
    cudaFuncSetAttribute(hmma_gemm<1>, cudaFuncAttributeMaxDynamicSharedMemorySize, DSMEM);
    cudaFuncSetAttribute(hmma_gemm<2>, cudaFuncAttributeMaxDynamicSharedMemorySize, DSMEM);

    // 1) LN1 stats + split
    batch_stats<<<Bb, 256>>>(x, mu1, rstd1);
    ln_split<<<(Mc * Lc / 4) / 256, 256>>>(x, mu1, rstd1, ln1w, ln1b, a1h, a1l);
    // 2) operand prep
    build_ct<<<dim3(2, Lc), 256>>>(w, cth, ctl);
    transpose_split<<<dim3(Hc / 32, Lc / 32), dim3(32, 8)>>>(w1, w1th, w1tl, Lc, Hc);
    transpose_split<<<dim3(Lc / 32, Hc / 32), dim3(32, 8)>>>(w2, w2th, w2tl, Hc, Lc);
    // 3) y = LN1(x) @ C        M=32768 K=512 N=512
    hmma_gemm<0><<<dim3(Lc / 128, Mc / 128), 256, DSMEM>>>(
        a1h, a1l, cth, ctl, y, nullptr, nullptr, nullptr, nullptr, Lc, Lc);
    // 4) LN2 stats + split
    batch_stats<<<Bb, 256>>>(y, mu2, rstd2);
    ln_split<<<(Mc * Lc / 4) / 256, 256>>>(y, mu2, rstd2, ln2w, ln2b, a2h, a2l);
    // 5) z = relu(LN2(y) @ w1 + b1)   M=32768 K=512 N=2048, split-bf16 out
    hmma_gemm<1><<<dim3(Hc / 128, Mc / 128), 256, DSMEM>>>(
        a2h, a2l, w1th, w1tl, nullptr, zh, zl, b1, nullptr, Lc, Hc);
    // 6) out = z @ w2 + b2 + x        M=32768 K=2048 N=512
    hmma_gemm<2><<<dim3(Lc / 128, Mc / 128), 256, DSMEM>>>(
        zh, zl, w2th, w2tl, out, nullptr, nullptr, b2, x, Hc, Lc);
}

// round 5
// speedup vs baseline: 3.9286x; 1.4168x over previous
#include <cuda_runtime.h>
#include <cuda_fp16.h>
#include <math.h>
#include <stdint.h>

#define Bb  512
#define P1c 64
#define Lc  512
#define Hc  2048
#define Mc  (Bb * P1c)   // 32768 rows

// ---------------- scratch ----------------
__device__ float g_mu1[Bb];
__device__ float g_rstd1[Bb];
__device__ float g_mu2[Bb];
__device__ float g_rstd2[Bb];
__device__ float g_y[(size_t)Mc * Lc];                 // 64 MB fp32
__device__ __half g_a1[(size_t)Mc * Lc];               // LN1(x) fp16
__device__ __half g_a2[(size_t)Mc * Lc];               // LN2(y) fp16
__device__ __half g_cth[Lc * Lc];                      // C^T hi [N,K]
__device__ __half g_ctl[Lc * Lc];
__device__ __half g_w1th[(size_t)Hc * Lc];             // w1^T hi [2048,512]
__device__ __half g_w1tl[(size_t)Hc * Lc];
__device__ __half g_w2th[(size_t)Lc * Hc];             // w2^T hi [512,2048]
__device__ __half g_w2tl[(size_t)Lc * Hc];
__device__ __half g_z[(size_t)Mc * Hc];                // FFN hidden fp16, 128 MB

// ---------------- helpers ----------------
__device__ __forceinline__ uint32_t smem_u32(const void* p) {
    uint32_t a;
    asm("{ .reg .u64 t; cvta.to.shared.u64 t, %1; cvt.u32.u64 %0, t; }" : "=r"(a) : "l"(p));
    return a;
}
__device__ __forceinline__ void split_h(float v, unsigned short& h, unsigned short& l) {
    __half hb = __float2half(v);
    float rem = v - __half2float(hb);
    __half lb = __float2half(rem);
    h = __half_as_ushort(hb);
    l = __half_as_ushort(lb);
}
__device__ __forceinline__ void cp16(uint32_t dst, const void* src) {
    asm volatile("cp.async.cg.shared.global [%0], [%1], 16;"
                 :: "r"(dst), "l"((unsigned long long)__cvta_generic_to_global(src)));
}
__device__ __forceinline__ void ldm4(uint32_t addr, uint32_t* r) {
    asm volatile("ldmatrix.sync.aligned.m8n8.x4.shared.b16 {%0,%1,%2,%3}, [%4];"
                 : "=r"(r[0]), "=r"(r[1]), "=r"(r[2]), "=r"(r[3]) : "r"(addr));
}
__device__ __forceinline__ void mma16816(float* c, const uint32_t* a,
                                         uint32_t b0, uint32_t b1) {
    asm volatile(
        "mma.sync.aligned.m16n8k16.row.col.f32.f16.f16.f32 "
        "{%0,%1,%2,%3}, {%4,%5,%6,%7}, {%8,%9}, {%0,%1,%2,%3};"
        : "+f"(c[0]), "+f"(c[1]), "+f"(c[2]), "+f"(c[3])
        : "r"(a[0]), "r"(a[1]), "r"(a[2]), "r"(a[3]), "r"(b0), "r"(b1));
}

// ---------------- per-batch mean / rstd over (P1, L) ----------------
__global__ void batch_stats(const float* __restrict__ x,
                            float* __restrict__ mu, float* __restrict__ rstd) {
    const int NPER = P1c * Lc;
    const int b = blockIdx.x;
    const float4* xb = reinterpret_cast<const float4*>(x) + (size_t)b * (NPER / 4);
    float s = 0.f, ss = 0.f;
    for (int i = threadIdx.x; i < NPER / 4; i += blockDim.x) {
        float4 v = xb[i];
        s  += (v.x + v.y) + (v.z + v.w);
        ss += v.x * v.x + v.y * v.y + v.z * v.z + v.w * v.w;
    }
    __shared__ float sh_s[32], sh_ss[32];
    const int lane = threadIdx.x & 31, wid = threadIdx.x >> 5;
    for (int o = 16; o > 0; o >>= 1) {
        s  += __shfl_xor_sync(0xFFFFFFFFu, s,  o);
        ss += __shfl_xor_sync(0xFFFFFFFFu, ss, o);
    }
    if (lane == 0) { sh_s[wid] = s; sh_ss[wid] = ss; }
    __syncthreads();
    if (wid == 0) {
        const int nw = blockDim.x >> 5;
        s  = (lane < nw) ? sh_s[lane]  : 0.f;
        ss = (lane < nw) ? sh_ss[lane] : 0.f;
        for (int o = 16; o > 0; o >>= 1) {
            s  += __shfl_xor_sync(0xFFFFFFFFu, s,  o);
            ss += __shfl_xor_sync(0xFFFFFFFFu, ss, o);
        }
        if (lane == 0) {
            float m = s / NPER;
            float var = ss / NPER - m * m;
            mu[b] = m;
            rstd[b] = rsqrtf(var + 1e-5f);
        }
    }
}

// ---------------- LN -> fp16 ----------------
__global__ void ln_fp16(const float* __restrict__ x,
                        const float* __restrict__ mu, const float* __restrict__ rstd,
                        const float* __restrict__ g, const float* __restrict__ bb,
                        __half* __restrict__ out) {
    size_t idx = (size_t)blockIdx.x * blockDim.x + threadIdx.x;
    int row = (int)(idx >> 7);
    int c4  = (int)(idx & 127) << 2;
    int b = row >> 6, p = row & 63;
    float m = mu[b], r = rstd[b];
    float4 v  = *(const float4*)&x[(size_t)row * Lc + c4];
    float4 gv = *(const float4*)&g[p * Lc + c4];
    float4 bv = *(const float4*)&bb[p * Lc + c4];
    ushort4 h4;
    h4.x = __half_as_ushort(__float2half((v.x - m) * r * gv.x + bv.x));
    h4.y = __half_as_ushort(__float2half((v.y - m) * r * gv.y + bv.y));
    h4.z = __half_as_ushort(__float2half((v.z - m) * r * gv.z + bv.z));
    h4.w = __half_as_ushort(__float2half((v.w - m) * r * gv.w + bv.w));
    *(ushort4*)&out[(size_t)row * Lc + c4] = h4;
}

// ---------------- Ct[n][k] = w[(n-k)&511]/sqrt(L), fp16 split ----------------
__global__ void build_ct(const float* __restrict__ w,
                         __half* __restrict__ hi, __half* __restrict__ lo) {
    int k = blockIdx.x * blockDim.x + threadIdx.x;
    int n = blockIdx.y;
    float v = w[(n - k) & (Lc - 1)] * 0.04419417382415922f;
    unsigned short h, l;
    split_h(v, h, l);
    hi[n * Lc + k] = __ushort_as_half(h);
    lo[n * Lc + k] = __ushort_as_half(l);
}

// ---------------- transpose + fp16 split: [K,N] fp32 -> [N,K] ----------------
__global__ void transpose_split(const float* __restrict__ in,
                                __half* __restrict__ hi, __half* __restrict__ lo,
                                int K, int N) {
    __shared__ float t[32][33];
    int n0 = blockIdx.x * 32, k0 = blockIdx.y * 32;
    int tx = threadIdx.x, ty = threadIdx.y;
    for (int i = ty; i < 32; i += 8)
        t[i][tx] = in[(size_t)(k0 + i) * N + n0 + tx];
    __syncthreads();
    for (int i = ty; i < 32; i += 8) {
        float v = t[tx][i];
        size_t o = (size_t)(n0 + i) * K + k0 + tx;
        unsigned short h, l;
        split_h(v, h, l);
        hi[o] = __ushort_as_half(h);
        lo[o] = __ushort_as_half(l);
    }
}

// ---------------- HMMA fp16 2-product GEMM ----------------
// CTA tile 128x128, BK=32, 8 warps (4M x 2N), warp tile 32x64.
// D = A * (Bhi + Blo), fp32 accumulate. 2-stage, 2 CTAs/SM, one sync/kt.
// EPI 0: Dout=acc; 1: Z = fp16(relu(acc+bias)); 2: Dout=acc+bias+res.
#define RSTRIDE 80                      // 64B data + 16B pad per k-row
#define MTILE_B (128 * RSTRIDE)         // 10240 per matrix
#define STG     (3 * MTILE_B)           // A, Bhi, Blo = 30720
#define DSMEM   (2 * STG)               // 61440

template <int EPI>
__global__ void __launch_bounds__(256, 2)
hmma_gemm(const __half* __restrict__ A,
          const __half* __restrict__ Bhi, const __half* __restrict__ Blo,
          float* __restrict__ Dout, __half* __restrict__ Z,
          const float* __restrict__ bias, const float* __restrict__ res,
          int K, int N) {
    extern __shared__ char smem[];
    const uint32_t sb = smem_u32(smem);
    const int tid = threadIdx.x, wid = tid >> 5, lane = tid & 31;
    const int wy = wid & 3, wx = wid >> 2;            // 4 M-warps x 2 N-warps
    const int m0 = blockIdx.y * 128, n0 = blockIdx.x * 128;

    const uint32_t offA = (uint32_t)((wy * 32 + (lane & 7) + ((lane >> 3) & 1) * 8) * RSTRIDE
                                     + (lane >> 4) * 16);
    const uint32_t offB = (uint32_t)((wx * 64 + (lane & 7) + (lane >> 4) * 8) * RSTRIDE
                                     + ((lane >> 3) & 1) * 16);

    auto load_stage = [&](int s, int kt) {
        const uint32_t ab = sb + s * STG;
#pragma unroll
        for (int i = 0; i < 2; i++) {
            const int j = tid + (i << 8);       // 0..511
            const int row = j >> 2, c = j & 3;
            const uint32_t off = row * RSTRIDE + c * 16;
            const size_t asrc = (size_t)(m0 + row) * K + (size_t)kt * 32 + c * 8;
            const size_t bsrc = (size_t)(n0 + row) * K + (size_t)kt * 32 + c * 8;
            cp16(ab + off,               A   + asrc);
            cp16(ab + MTILE_B + off,     Bhi + bsrc);
            cp16(ab + 2 * MTILE_B + off, Blo + bsrc);
        }
        asm volatile("cp.async.commit_group;");
    };

    float acc[2][8][4];
#pragma unroll
    for (int mi = 0; mi < 2; mi++)
#pragma unroll
        for (int ni = 0; ni < 8; ni++)
#pragma unroll
            for (int q = 0; q < 4; q++) acc[mi][ni][q] = 0.f;

    const int nkt = K >> 5;
    load_stage(0, 0);

    for (int kt = 0; kt < nkt; kt++) {
        asm volatile("cp.async.wait_group 0;" ::: "memory");
        __syncthreads();
        if (kt + 1 < nkt) load_stage((kt + 1) & 1, kt + 1);

        const uint32_t st = sb + (kt & 1) * STG;
#pragma unroll
        for (int kk = 0; kk < 2; kk++) {
            uint32_t ah[2][4];
#pragma unroll
            for (int mi = 0; mi < 2; mi++)
                ldm4(st + offA + mi * (16 * RSTRIDE) + kk * 32, ah[mi]);
#pragma unroll
            for (int half = 0; half < 2; half++) {
                uint32_t bh[2][4], bl[2][4];
#pragma unroll
                for (int n2 = 0; n2 < 2; n2++) {
                    const uint32_t b = st + MTILE_B + offB
                                       + (half * 2 + n2) * (16 * RSTRIDE) + kk * 32;
                    ldm4(b, bh[n2]);
                    ldm4(b + MTILE_B, bl[n2]);
                }
#pragma unroll
                for (int mi = 0; mi < 2; mi++)
#pragma unroll
                    for (int n2 = 0; n2 < 2; n2++) {
                        const int nf = half * 2 + n2;
                        mma16816(acc[mi][nf * 2 + 0], ah[mi], bh[n2][0], bh[n2][1]);
                        mma16816(acc[mi][nf * 2 + 1], ah[mi], bh[n2][2], bh[n2][3]);
                        mma16816(acc[mi][nf * 2 + 0], ah[mi], bl[n2][0], bl[n2][1]);
                        mma16816(acc[mi][nf * 2 + 1], ah[mi], bl[n2][2], bl[n2][3]);
                    }
            }
        }
    }

    // ---- epilogue ----
    const int r0 = m0 + wy * 32 + (lane >> 2);
    const int cbase = n0 + wx * 64 + (lane & 3) * 2;
#pragma unroll
    for (int mi = 0; mi < 2; mi++) {
#pragma unroll
        for (int ni = 0; ni < 8; ni++) {
            const int col = cbase + ni * 8;
            const int ra = r0 + mi * 16;
            const int rb = ra + 8;
            float* c = acc[mi][ni];
            if (EPI == 0) {
                *(float2*)&Dout[(size_t)ra * N + col] = make_float2(c[0], c[1]);
                *(float2*)&Dout[(size_t)rb * N + col] = make_float2(c[2], c[3]);
            } else if (EPI == 1) {
                const float2 bq = *(const float2*)&bias[col];
                ushort2 h0, h1;
                h0.x = __half_as_ushort(__float2half(fmaxf(c[0] + bq.x, 0.f)));
                h0.y = __half_as_ushort(__float2half(fmaxf(c[1] + bq.y, 0.f)));
                h1.x = __half_as_ushort(__float2half(fmaxf(c[2] + bq.x, 0.f)));
                h1.y = __half_as_ushort(__float2half(fmaxf(c[3] + bq.y, 0.f)));
                *(ushort2*)&Z[(size_t)ra * N + col] = h0;
                *(ushort2*)&Z[(size_t)rb * N + col] = h1;
            } else {
                const float2 bq = *(const float2*)&bias[col];
                const float2 q0 = *(const float2*)&res[(size_t)ra * N + col];
                const float2 q1 = *(const float2*)&res[(size_t)rb * N + col];
                *(float2*)&Dout[(size_t)ra * N + col] =
                    make_float2(c[0] + bq.x + q0.x, c[1] + bq.y + q0.y);
                *(float2*)&Dout[(size_t)rb * N + col] =
                    make_float2(c[2] + bq.x + q1.x, c[3] + bq.y + q1.y);
            }
        }
    }
}

// ---------------- launcher ----------------
extern "C" void kernel_launch(void* const* d_in, const int* in_sizes, int n_in,
                              void* d_out, int out_size) {
    const float* x    = (const float*)d_in[0];
    const float* w    = (const float*)d_in[1];
    const float* ln1w = (const float*)d_in[2];
    const float* ln1b = (const float*)d_in[3];
    const float* ln2w = (const float*)d_in[4];
    const float* ln2b = (const float*)d_in[5];
    const float* w1   = (const float*)d_in[6];
    const float* b1   = (const float*)d_in[7];
    const float* w2   = (const float*)d_in[8];
    const float* b2   = (const float*)d_in[9];
    float* out = (float*)d_out;

    float *mu1, *rstd1, *mu2, *rstd2, *y;
    __half *a1, *a2, *cth, *ctl, *w1th, *w1tl, *w2th, *w2tl, *z;
    cudaGetSymbolAddress((void**)&mu1,   g_mu1);
    cudaGetSymbolAddress((void**)&rstd1, g_rstd1);
    cudaGetSymbolAddress((void**)&mu2,   g_mu2);
    cudaGetSymbolAddress((void**)&rstd2, g_rstd2);
    cudaGetSymbolAddress((void**)&y,     g_y);
    cudaGetSymbolAddress((void**)&a1,    g_a1);
    cudaGetSymbolAddress((void**)&a2,    g_a2);
    cudaGetSymbolAddress((void**)&cth,   g_cth);
    cudaGetSymbolAddress((void**)&ctl,   g_ctl);
    cudaGetSymbolAddress((void**)&w1th,  g_w1th);
    cudaGetSymbolAddress((void**)&w1tl,  g_w1tl);
    cudaGetSymbolAddress((void**)&w2th,  g_w2th);
    cudaGetSymbolAddress((void**)&w2tl,  g_w2tl);
    cudaGetSymbolAddress((void**)&z,     g_z);

    cudaFuncSetAttribute(hmma_gemm<0>, cudaFuncAttributeMaxDynamicSharedMemorySize, DSMEM);
    cudaFuncSetAttribute(hmma_gemm<1>, cudaFuncAttributeMaxDynamicSharedMemorySize, DSMEM);
    cudaFuncSetAttribute(hmma_gemm<2>, cudaFuncAttributeMaxDynamicSharedMemorySize, DSMEM);

    // 1) LN1 stats + fp16
    batch_stats<<<Bb, 256>>>(x, mu1, rstd1);
    ln_fp16<<<(Mc * Lc / 4) / 256, 256>>>(x, mu1, rstd1, ln1w, ln1b, a1);
    // 2) operand prep (B-side fp16 splits)
    build_ct<<<dim3(2, Lc), 256>>>(w, cth, ctl);
    transpose_split<<<dim3(Hc / 32, Lc / 32), dim3(32, 8)>>>(w1, w1th, w1tl, Lc, Hc);
    transpose_split<<<dim3(Lc / 32, Hc / 32), dim3(32, 8)>>>(w2, w2th, w2tl, Hc, Lc);
    // 3) y = LN1(x) @ C        M=32768 K=512 N=512
    hmma_gemm<0><<<dim3(Lc / 128, Mc / 128), 256, DSMEM>>>(
        a1, cth, ctl, y, nullptr, nullptr, nullptr, Lc, Lc);
    // 4) LN2 stats + fp16
    batch_stats<<<Bb, 256>>>(y, mu2, rstd2);
    ln_fp16<<<(Mc * Lc / 4) / 256, 256>>>(y, mu2, rstd2, ln2w, ln2b, a2);
    // 5) z = fp16(relu(LN2(y) @ w1 + b1))   M=32768 K=512 N=2048
    hmma_gemm<1><<<dim3(Hc / 128, Mc / 128), 256, DSMEM>>>(
        a2, w1th, w1tl, nullptr, z, b1, nullptr, Lc, Hc);
    // 6) out = z @ w2 + b2 + x              M=32768 K=2048 N=512
    hmma_gemm<2><<<dim3(Lc / 128, Mc / 128), 256, DSMEM>>>(
        z, w2th, w2tl, out, nullptr, b2, x, Hc, Lc);
}

// round 6
// speedup vs baseline: 6.2212x; 1.5836x over previous
#include <cuda_runtime.h>
#include <cuda_fp16.h>
#include <math.h>
#include <stdint.h>

#define Bb  512
#define P1c 64
#define Lc  512
#define Hc  2048
#define Mc  (Bb * P1c)   // 32768 rows

// ---------------- scratch ----------------
__device__ float g_mu1[Bb];
__device__ float g_rstd1[Bb];
__device__ float g_mu2[Bb];
__device__ float g_rstd2[Bb];
__device__ float g_y[(size_t)Mc * Lc];                 // 64 MB fp32
__device__ __half g_a1[(size_t)Mc * Lc];               // LN1(x) fp16
__device__ __half g_a2[(size_t)Mc * Lc];               // LN2(y) fp16
__device__ __half g_ct[Lc * Lc];                       // C^T [N,K] fp16
__device__ __half g_w1t[(size_t)Hc * Lc];              // w1^T [2048,512] fp16
__device__ __half g_w2t[(size_t)Lc * Hc];              // w2^T [512,2048] fp16
__device__ __half g_z[(size_t)Mc * Hc];                // FFN hidden fp16, 128 MB

// ---------------- helpers ----------------
__device__ __forceinline__ uint32_t smem_u32(const void* p) {
    uint32_t a;
    asm("{ .reg .u64 t; cvta.to.shared.u64 t, %1; cvt.u32.u64 %0, t; }" : "=r"(a) : "l"(p));
    return a;
}
__device__ __forceinline__ void cp16(uint32_t dst, const void* src) {
    asm volatile("cp.async.cg.shared.global [%0], [%1], 16;"
                 :: "r"(dst), "l"((unsigned long long)__cvta_generic_to_global(src)));
}
__device__ __forceinline__ void ldm4(uint32_t addr, uint32_t* r) {
    asm volatile("ldmatrix.sync.aligned.m8n8.x4.shared.b16 {%0,%1,%2,%3}, [%4];"
                 : "=r"(r[0]), "=r"(r[1]), "=r"(r[2]), "=r"(r[3]) : "r"(addr));
}
__device__ __forceinline__ void mma16816(float* c, const uint32_t* a,
                                         uint32_t b0, uint32_t b1) {
    asm volatile(
        "mma.sync.aligned.m16n8k16.row.col.f32.f16.f16.f32 "
        "{%0,%1,%2,%3}, {%4,%5,%6,%7}, {%8,%9}, {%0,%1,%2,%3};"
        : "+f"(c[0]), "+f"(c[1]), "+f"(c[2]), "+f"(c[3])
        : "r"(a[0]), "r"(a[1]), "r"(a[2]), "r"(a[3]), "r"(b0), "r"(b1));
}

// ---------------- per-batch mean / rstd over (P1, L) ----------------
__global__ void batch_stats(const float* __restrict__ x,
                            float* __restrict__ mu, float* __restrict__ rstd) {
    const int NPER = P1c * Lc;
    const int b = blockIdx.x;
    const float4* xb = reinterpret_cast<const float4*>(x) + (size_t)b * (NPER / 4);
    float s = 0.f, ss = 0.f;
    for (int i = threadIdx.x; i < NPER / 4; i += blockDim.x) {
        float4 v = xb[i];
        s  += (v.x + v.y) + (v.z + v.w);
        ss += v.x * v.x + v.y * v.y + v.z * v.z + v.w * v.w;
    }
    __shared__ float sh_s[32], sh_ss[32];
    const int lane = threadIdx.x & 31, wid = threadIdx.x >> 5;
    for (int o = 16; o > 0; o >>= 1) {
        s  += __shfl_xor_sync(0xFFFFFFFFu, s,  o);
        ss += __shfl_xor_sync(0xFFFFFFFFu, ss, o);
    }
    if (lane == 0) { sh_s[wid] = s; sh_ss[wid] = ss; }
    __syncthreads();
    if (wid == 0) {
        const int nw = blockDim.x >> 5;
        s  = (lane < nw) ? sh_s[lane]  : 0.f;
        ss = (lane < nw) ? sh_ss[lane] : 0.f;
        for (int o = 16; o > 0; o >>= 1) {
            s  += __shfl_xor_sync(0xFFFFFFFFu, s,  o);
            ss += __shfl_xor_sync(0xFFFFFFFFu, ss, o);
        }
        if (lane == 0) {
            float m = s / NPER;
            float var = ss / NPER - m * m;
            mu[b] = m;
            rstd[b] = rsqrtf(var + 1e-5f);
        }
    }
}

// ---------------- LN -> fp16 ----------------
__global__ void ln_fp16(const float* __restrict__ x,
                        const float* __restrict__ mu, const float* __restrict__ rstd,
                        const float* __restrict__ g, const float* __restrict__ bb,
                        __half* __restrict__ out) {
    size_t idx = (size_t)blockIdx.x * blockDim.x + threadIdx.x;
    int row = (int)(idx >> 7);
    int c4  = (int)(idx & 127) << 2;
    int b = row >> 6, p = row & 63;
    float m = mu[b], r = rstd[b];
    float4 v  = *(const float4*)&x[(size_t)row * Lc + c4];
    float4 gv = *(const float4*)&g[p * Lc + c4];
    float4 bv = *(const float4*)&bb[p * Lc + c4];
    ushort4 h4;
    h4.x = __half_as_ushort(__float2half((v.x - m) * r * gv.x + bv.x));
    h4.y = __half_as_ushort(__float2half((v.y - m) * r * gv.y + bv.y));
    h4.z = __half_as_ushort(__float2half((v.z - m) * r * gv.z + bv.z));
    h4.w = __half_as_ushort(__float2half((v.w - m) * r * gv.w + bv.w));
    *(ushort4*)&out[(size_t)row * Lc + c4] = h4;
}

// ---------------- Ct[n][k] = w[(n-k)&511]/sqrt(L), fp16 ----------------
__global__ void build_ct(const float* __restrict__ w, __half* __restrict__ ct) {
    int k = blockIdx.x * blockDim.x + threadIdx.x;
    int n = blockIdx.y;
    ct[n * Lc + k] = __float2half(w[(n - k) & (Lc - 1)] * 0.04419417382415922f);
}

// ---------------- transpose -> fp16: [K,N] fp32 -> [N,K] ----------------
__global__ void transpose_h(const float* __restrict__ in, __half* __restrict__ outp,
                            int K, int N) {
    __shared__ float t[32][33];
    int n0 = blockIdx.x * 32, k0 = blockIdx.y * 32;
    int tx = threadIdx.x, ty = threadIdx.y;
    for (int i = ty; i < 32; i += 8)
        t[i][tx] = in[(size_t)(k0 + i) * N + n0 + tx];
    __syncthreads();
    for (int i = ty; i < 32; i += 8)
        outp[(size_t)(n0 + i) * K + k0 + tx] = __float2half(t[tx][i]);
}

// ---------------- HMMA fp16 GEMM ----------------
// CTA tile 128x128, BK=32, 8 warps (4M x 2N), warp tile 32x64.
// D = A*B, fp32 accumulate. 3-stage cp.async pipeline, 2 CTAs/SM, one sync/kt.
// EPI 0: Dout=acc; 1: Z = fp16(relu(acc+bias)); 2: Dout=acc+bias+res.
#define RSTRIDE 80                      // 64B data + 16B pad per k-row
#define MTILE_B (128 * RSTRIDE)         // 10240 per matrix
#define STG     (2 * MTILE_B)           // A, B = 20480
#define DSMEM   (3 * STG)               // 61440

template <int EPI>
__global__ void __launch_bounds__(256, 2)
hmma_gemm(const __half* __restrict__ A, const __half* __restrict__ B,
          float* __restrict__ Dout, __half* __restrict__ Z,
          const float* __restrict__ bias, const float* __restrict__ res,
          int K, int N) {
    extern __shared__ char smem[];
    const uint32_t sb = smem_u32(smem);
    const int tid = threadIdx.x, wid = tid >> 5, lane = tid & 31;
    const int wy = wid & 3, wx = wid >> 2;            // 4 M-warps x 2 N-warps
    const int m0 = blockIdx.y * 128, n0 = blockIdx.x * 128;

    const uint32_t offA = (uint32_t)((wy * 32 + (lane & 7) + ((lane >> 3) & 1) * 8) * RSTRIDE
                                     + (lane >> 4) * 16);
    const uint32_t offB = (uint32_t)((wx * 64 + (lane & 7) + (lane >> 4) * 8) * RSTRIDE
                                     + ((lane >> 3) & 1) * 16);

    auto load_stage = [&](int s, int kt) {
        const uint32_t ab = sb + s * STG;
#pragma unroll
        for (int i = 0; i < 2; i++) {
            const int j = tid + (i << 8);       // 0..511
            const int row = j >> 2, c = j & 3;
            const uint32_t off = row * RSTRIDE + c * 16;
            const size_t asrc = (size_t)(m0 + row) * K + (size_t)kt * 32 + c * 8;
            const size_t bsrc = (size_t)(n0 + row) * K + (size_t)kt * 32 + c * 8;
            cp16(ab + off,           A + asrc);
            cp16(ab + MTILE_B + off, B + bsrc);
        }
        asm volatile("cp.async.commit_group;");
    };

    float acc[2][8][4];
#pragma unroll
    for (int mi = 0; mi < 2; mi++)
#pragma unroll
        for (int ni = 0; ni < 8; ni++)
#pragma unroll
            for (int q = 0; q < 4; q++) acc[mi][ni][q] = 0.f;

    const int nkt = K >> 5;       // >= 16 always here
    load_stage(0, 0);
    load_stage(1, 1);

    int scur = 0, snxt = 2;
    for (int kt = 0; kt < nkt; kt++) {
        if (kt + 1 < nkt) asm volatile("cp.async.wait_group 1;" ::: "memory");
        else              asm volatile("cp.async.wait_group 0;" ::: "memory");
        __syncthreads();
        if (kt + 2 < nkt) {
            load_stage(snxt, kt + 2);
            snxt = (snxt == 2) ? 0 : snxt + 1;
        }

        const uint32_t st = sb + scur * STG;
        scur = (scur == 2) ? 0 : scur + 1;
#pragma unroll
        for (int kk = 0; kk < 2; kk++) {
            uint32_t ah[2][4];
#pragma unroll
            for (int mi = 0; mi < 2; mi++)
                ldm4(st + offA + mi * (16 * RSTRIDE) + kk * 32, ah[mi]);
#pragma unroll
            for (int half = 0; half < 2; half++) {
                uint32_t bf[2][4];
#pragma unroll
                for (int n2 = 0; n2 < 2; n2++)
                    ldm4(st + MTILE_B + offB + (half * 2 + n2) * (16 * RSTRIDE) + kk * 32,
                         bf[n2]);
#pragma unroll
                for (int mi = 0; mi < 2; mi++)
#pragma unroll
                    for (int n2 = 0; n2 < 2; n2++) {
                        const int nf = half * 2 + n2;
                        mma16816(acc[mi][nf * 2 + 0], ah[mi], bf[n2][0], bf[n2][1]);
                        mma16816(acc[mi][nf * 2 + 1], ah[mi], bf[n2][2], bf[n2][3]);
                    }
            }
        }
    }

    // ---- epilogue ----
    const int r0 = m0 + wy * 32 + (lane >> 2);
    const int cbase = n0 + wx * 64 + (lane & 3) * 2;
#pragma unroll
    for (int mi = 0; mi < 2; mi++) {
#pragma unroll
        for (int ni = 0; ni < 8; ni++) {
            const int col = cbase + ni * 8;
            const int ra = r0 + mi * 16;
            const int rb = ra + 8;
            float* c = acc[mi][ni];
            if (EPI == 0) {
                *(float2*)&Dout[(size_t)ra * N + col] = make_float2(c[0], c[1]);
                *(float2*)&Dout[(size_t)rb * N + col] = make_float2(c[2], c[3]);
            } else if (EPI == 1) {
                const float2 bq = *(const float2*)&bias[col];
                ushort2 h0, h1;
                h0.x = __half_as_ushort(__float2half(fmaxf(c[0] + bq.x, 0.f)));
                h0.y = __half_as_ushort(__float2half(fmaxf(c[1] + bq.y, 0.f)));
                h1.x = __half_as_ushort(__float2half(fmaxf(c[2] + bq.x, 0.f)));
                h1.y = __half_as_ushort(__float2half(fmaxf(c[3] + bq.y, 0.f)));
                *(ushort2*)&Z[(size_t)ra * N + col] = h0;
                *(ushort2*)&Z[(size_t)rb * N + col] = h1;
            } else {
                const float2 bq = *(const float2*)&bias[col];
                const float2 q0 = *(const float2*)&res[(size_t)ra * N + col];
                const float2 q1 = *(const float2*)&res[(size_t)rb * N + col];
                *(float2*)&Dout[(size_t)ra * N + col] =
                    make_float2(c[0] + bq.x + q0.x, c[1] + bq.y + q0.y);
                *(float2*)&Dout[(size_t)rb * N + col] =
                    make_float2(c[2] + bq.x + q1.x, c[3] + bq.y + q1.y);
            }
        }
    }
}

// ---------------- launcher ----------------
extern "C" void kernel_launch(void* const* d_in, const int* in_sizes, int n_in,
                              void* d_out, int out_size) {
    const float* x    = (const float*)d_in[0];
    const float* w    = (const float*)d_in[1];
    const float* ln1w = (const float*)d_in[2];
    const float* ln1b = (const float*)d_in[3];
    const float* ln2w = (const float*)d_in[4];
    const float* ln2b = (const float*)d_in[5];
    const float* w1   = (const float*)d_in[6];
    const float* b1   = (const float*)d_in[7];
    const float* w2   = (const float*)d_in[8];
    const float* b2   = (const float*)d_in[9];
    float* out = (float*)d_out;

    float *mu1, *rstd1, *mu2, *rstd2, *y;
    __half *a1, *a2, *ct, *w1t, *w2t, *z;
    cudaGetSymbolAddress((void**)&mu1,   g_mu1);
    cudaGetSymbolAddress((void**)&rstd1, g_rstd1);
    cudaGetSymbolAddress((void**)&mu2,   g_mu2);
    cudaGetSymbolAddress((void**)&rstd2, g_rstd2);
    cudaGetSymbolAddress((void**)&y,     g_y);
    cudaGetSymbolAddress((void**)&a1,    g_a1);
    cudaGetSymbolAddress((void**)&a2,    g_a2);
    cudaGetSymbolAddress((void**)&ct,    g_ct);
    cudaGetSymbolAddress((void**)&w1t,   g_w1t);
    cudaGetSymbolAddress((void**)&w2t,   g_w2t);
    cudaGetSymbolAddress((void**)&z,     g_z);

    cudaFuncSetAttribute(hmma_gemm<0>, cudaFuncAttributeMaxDynamicSharedMemorySize, DSMEM);
    cudaFuncSetAttribute(hmma_gemm<1>, cudaFuncAttributeMaxDynamicSharedMemorySize, DSMEM);
    cudaFuncSetAttribute(hmma_gemm<2>, cudaFuncAttributeMaxDynamicSharedMemorySize, DSMEM);

    // 1) LN1 stats + fp16
    batch_stats<<<Bb, 256>>>(x, mu1, rstd1);
    ln_fp16<<<(Mc * Lc / 4) / 256, 256>>>(x, mu1, rstd1, ln1w, ln1b, a1);
    // 2) operand prep (fp16)
    build_ct<<<dim3(2, Lc), 256>>>(w, ct);
    transpose_h<<<dim3(Hc / 32, Lc / 32), dim3(32, 8)>>>(w1, w1t, Lc, Hc);
    transpose_h<<<dim3(Lc / 32, Hc / 32), dim3(32, 8)>>>(w2, w2t, Hc, Lc);
    // 3) y = LN1(x) @ C        M=32768 K=512 N=512
    hmma_gemm<0><<<dim3(Lc / 128, Mc / 128), 256, DSMEM>>>(
        a1, ct, y, nullptr, nullptr, nullptr, Lc, Lc);
    // 4) LN2 stats + fp16
    batch_stats<<<Bb, 256>>>(y, mu2, rstd2);
    ln_fp16<<<(Mc * Lc / 4) / 256, 256>>>(y, mu2, rstd2, ln2w, ln2b, a2);
    // 5) z = fp16(relu(LN2(y) @ w1 + b1))   M=32768 K=512 N=2048
    hmma_gemm<1><<<dim3(Hc / 128, Mc / 128), 256, DSMEM>>>(
        a2, w1t, nullptr, z, b1, nullptr, Lc, Hc);
    // 6) out = z @ w2 + b2 + x              M=32768 K=2048 N=512
    hmma_gemm<2><<<dim3(Lc / 128, Mc / 128), 256, DSMEM>>>(
        z, w2t, out, nullptr, b2, x, Hc, Lc);
}

// round 7
// speedup vs baseline: 6.4503x; 1.0368x over previous
#include <cuda_runtime.h>
#include <cuda_fp16.h>
#include <math.h>
#include <stdint.h>

#define Bb  512
#define P1c 64
#define Lc  512
#define Hc  2048
#define Mc  (Bb * P1c)   // 32768 rows

// ---------------- scratch ----------------
__device__ float g_mu1[Bb];
__device__ float g_rstd1[Bb];
__device__ float g_mu2[Bb];
__device__ float g_rstd2[Bb];
__device__ float g_ysum[Bb];
__device__ float g_ysumsq[Bb];
__device__ __half g_yh[(size_t)Mc * Lc];               // filtered y fp16, 32 MB
__device__ __half g_a1[(size_t)Mc * Lc];               // LN1(x) fp16
__device__ __half g_a2[(size_t)Mc * Lc];               // LN2(y) fp16
__device__ __half g_ct[Lc * Lc];                       // C^T [N,K] fp16
__device__ __half g_w1t[(size_t)Hc * Lc];              // w1^T [2048,512] fp16
__device__ __half g_w2t[(size_t)Lc * Hc];              // w2^T [512,2048] fp16
__device__ __half g_z[(size_t)Mc * Hc];                // FFN hidden fp16, 128 MB

// ---------------- helpers ----------------
__device__ __forceinline__ uint32_t smem_u32(const void* p) {
    uint32_t a;
    asm("{ .reg .u64 t; cvta.to.shared.u64 t, %1; cvt.u32.u64 %0, t; }" : "=r"(a) : "l"(p));
    return a;
}
__device__ __forceinline__ void cp16(uint32_t dst, const void* src) {
    asm volatile("cp.async.cg.shared.global [%0], [%1], 16;"
                 :: "r"(dst), "l"((unsigned long long)__cvta_generic_to_global(src)));
}
__device__ __forceinline__ void ldm4(uint32_t addr, uint32_t* r) {
    asm volatile("ldmatrix.sync.aligned.m8n8.x4.shared.b16 {%0,%1,%2,%3}, [%4];"
                 : "=r"(r[0]), "=r"(r[1]), "=r"(r[2]), "=r"(r[3]) : "r"(addr));
}
__device__ __forceinline__ void mma16816(float* c, const uint32_t* a,
                                         uint32_t b0, uint32_t b1) {
    asm volatile(
        "mma.sync.aligned.m16n8k16.row.col.f32.f16.f16.f32 "
        "{%0,%1,%2,%3}, {%4,%5,%6,%7}, {%8,%9}, {%0,%1,%2,%3};"
        : "+f"(c[0]), "+f"(c[1]), "+f"(c[2]), "+f"(c[3])
        : "r"(a[0]), "r"(a[1]), "r"(a[2]), "r"(a[3]), "r"(b0), "r"(b1));
}

// ---------------- per-batch mean / rstd over (P1, L) fp32 input ----------------
__global__ void batch_stats(const float* __restrict__ x,
                            float* __restrict__ mu, float* __restrict__ rstd) {
    const int NPER = P1c * Lc;
    const int b = blockIdx.x;
    const float4* xb = reinterpret_cast<const float4*>(x) + (size_t)b * (NPER / 4);
    float s = 0.f, ss = 0.f;
    for (int i = threadIdx.x; i < NPER / 4; i += blockDim.x) {
        float4 v = xb[i];
        s  += (v.x + v.y) + (v.z + v.w);
        ss += v.x * v.x + v.y * v.y + v.z * v.z + v.w * v.w;
    }
    __shared__ float sh_s[32], sh_ss[32];
    const int lane = threadIdx.x & 31, wid = threadIdx.x >> 5;
    for (int o = 16; o > 0; o >>= 1) {
        s  += __shfl_xor_sync(0xFFFFFFFFu, s,  o);
        ss += __shfl_xor_sync(0xFFFFFFFFu, ss, o);
    }
    if (lane == 0) { sh_s[wid] = s; sh_ss[wid] = ss; }
    __syncthreads();
    if (wid == 0) {
        const int nw = blockDim.x >> 5;
        s  = (lane < nw) ? sh_s[lane]  : 0.f;
        ss = (lane < nw) ? sh_ss[lane] : 0.f;
        for (int o = 16; o > 0; o >>= 1) {
            s  += __shfl_xor_sync(0xFFFFFFFFu, s,  o);
            ss += __shfl_xor_sync(0xFFFFFFFFu, ss, o);
        }
        if (lane == 0) {
            float m = s / NPER;
            float var = ss / NPER - m * m;
            mu[b] = m;
            rstd[b] = rsqrtf(var + 1e-5f);
        }
    }
}

// ---------------- zero per-batch accumulators ----------------
__global__ void zero_acc(float* __restrict__ s, float* __restrict__ ss) {
    int i = threadIdx.x + blockIdx.x * blockDim.x;
    if (i < Bb) { s[i] = 0.f; ss[i] = 0.f; }
}

// ---------------- finalize y stats ----------------
__global__ void finalize_stats(const float* __restrict__ s, const float* __restrict__ ss,
                               float* __restrict__ mu, float* __restrict__ rstd) {
    int i = threadIdx.x + blockIdx.x * blockDim.x;
    if (i < Bb) {
        const float inv = 1.f / (P1c * Lc);
        float m = s[i] * inv;
        float var = ss[i] * inv - m * m;
        mu[i] = m;
        rstd[i] = rsqrtf(var + 1e-5f);
    }
}

// ---------------- LN(fp32 in) -> fp16 ----------------
__global__ void ln_fp16(const float* __restrict__ x,
                        const float* __restrict__ mu, const float* __restrict__ rstd,
                        const float* __restrict__ g, const float* __restrict__ bb,
                        __half* __restrict__ out) {
    size_t idx = (size_t)blockIdx.x * blockDim.x + threadIdx.x;
    int row = (int)(idx >> 7);
    int c4  = (int)(idx & 127) << 2;
    int b = row >> 6, p = row & 63;
    float m = mu[b], r = rstd[b];
    float4 v  = *(const float4*)&x[(size_t)row * Lc + c4];
    float4 gv = *(const float4*)&g[p * Lc + c4];
    float4 bv = *(const float4*)&bb[p * Lc + c4];
    ushort4 h4;
    h4.x = __half_as_ushort(__float2half((v.x - m) * r * gv.x + bv.x));
    h4.y = __half_as_ushort(__float2half((v.y - m) * r * gv.y + bv.y));
    h4.z = __half_as_ushort(__float2half((v.z - m) * r * gv.z + bv.z));
    h4.w = __half_as_ushort(__float2half((v.w - m) * r * gv.w + bv.w));
    *(ushort4*)&out[(size_t)row * Lc + c4] = h4;
}

// ---------------- LN(fp16 in) -> fp16 ----------------
__global__ void ln_fp16_h(const __half* __restrict__ x,
                          const float* __restrict__ mu, const float* __restrict__ rstd,
                          const float* __restrict__ g, const float* __restrict__ bb,
                          __half* __restrict__ out) {
    size_t idx = (size_t)blockIdx.x * blockDim.x + threadIdx.x;
    int row = (int)(idx >> 7);
    int c4  = (int)(idx & 127) << 2;
    int b = row >> 6, p = row & 63;
    float m = mu[b], r = rstd[b];
    ushort4 xv = *(const ushort4*)&x[(size_t)row * Lc + c4];
    float4 gv = *(const float4*)&g[p * Lc + c4];
    float4 bv = *(const float4*)&bb[p * Lc + c4];
    ushort4 h4;
    h4.x = __half_as_ushort(__float2half((__half2float(__ushort_as_half(xv.x)) - m) * r * gv.x + bv.x));
    h4.y = __half_as_ushort(__float2half((__half2float(__ushort_as_half(xv.y)) - m) * r * gv.y + bv.y));
    h4.z = __half_as_ushort(__float2half((__half2float(__ushort_as_half(xv.z)) - m) * r * gv.z + bv.z));
    h4.w = __half_as_ushort(__float2half((__half2float(__ushort_as_half(xv.w)) - m) * r * gv.w + bv.w));
    *(ushort4*)&out[(size_t)row * Lc + c4] = h4;
}

// ---------------- Ct[n][k] = w[(n-k)&511]/sqrt(L), fp16 ----------------
__global__ void build_ct(const float* __restrict__ w, __half* __restrict__ ct) {
    int k = blockIdx.x * blockDim.x + threadIdx.x;
    int n = blockIdx.y;
    ct[n * Lc + k] = __float2half(w[(n - k) & (Lc - 1)] * 0.04419417382415922f);
}

// ---------------- transpose -> fp16: [K,N] fp32 -> [N,K] ----------------
__global__ void transpose_h(const float* __restrict__ in, __half* __restrict__ outp,
                            int K, int N) {
    __shared__ float t[32][33];
    int n0 = blockIdx.x * 32, k0 = blockIdx.y * 32;
    int tx = threadIdx.x, ty = threadIdx.y;
    for (int i = ty; i < 32; i += 8)
        t[i][tx] = in[(size_t)(k0 + i) * N + n0 + tx];
    __syncthreads();
    for (int i = ty; i < 32; i += 8)
        outp[(size_t)(n0 + i) * K + k0 + tx] = __float2half(t[tx][i]);
}

// ---------------- HMMA fp16 GEMM ----------------
// CTA tile 128x128, BK=32, 8 warps (4M x 2N), warp tile 32x64.
// D = A*B, fp32 accumulate. 3-stage cp.async pipeline, 2 CTAs/SM, one sync/kt.
// EPI 0: Dout=acc
// EPI 1: Z = fp16(relu(acc+bias))
// EPI 2: Dout=acc+bias+res
// EPI 3: Z = fp16(acc), plus per-batch sum/sumsq atomics (ysum/ysumsq)
#define RSTRIDE 80                      // 64B data + 16B pad per k-row
#define MTILE_B (128 * RSTRIDE)         // 10240 per matrix
#define STG     (2 * MTILE_B)           // A, B = 20480
#define DSMEM   (3 * STG)               // 61440

template <int EPI, int K, int N>
__global__ void __launch_bounds__(256, 2)
hmma_gemm(const __half* __restrict__ A, const __half* __restrict__ B,
          float* __restrict__ Dout, __half* __restrict__ Z,
          const float* __restrict__ bias, const float* __restrict__ res,
          float* __restrict__ ysum, float* __restrict__ ysumsq) {
    extern __shared__ char smem[];
    const uint32_t sb = smem_u32(smem);
    const int tid = threadIdx.x, wid = tid >> 5, lane = tid & 31;
    const int wy = wid & 3, wx = wid >> 2;            // 4 M-warps x 2 N-warps
    const int m0 = blockIdx.y * 128, n0 = blockIdx.x * 128;

    const uint32_t offA = (uint32_t)((wy * 32 + (lane & 7) + ((lane >> 3) & 1) * 8) * RSTRIDE
                                     + (lane >> 4) * 16);
    const uint32_t offB = (uint32_t)((wx * 64 + (lane & 7) + (lane >> 4) * 8) * RSTRIDE
                                     + ((lane >> 3) & 1) * 16);

    auto load_stage = [&](int s, int kt) {
        const uint32_t ab = sb + s * STG;
#pragma unroll
        for (int i = 0; i < 2; i++) {
            const int j = tid + (i << 8);       // 0..511
            const int row = j >> 2, c = j & 3;
            const uint32_t off = row * RSTRIDE + c * 16;
            const size_t asrc = (size_t)(m0 + row) * K + (size_t)kt * 32 + c * 8;
            const size_t bsrc = (size_t)(n0 + row) * K + (size_t)kt * 32 + c * 8;
            cp16(ab + off,           A + asrc);
            cp16(ab + MTILE_B + off, B + bsrc);
        }
        asm volatile("cp.async.commit_group;");
    };

    float acc[2][8][4];
#pragma unroll
    for (int mi = 0; mi < 2; mi++)
#pragma unroll
        for (int ni = 0; ni < 8; ni++)
#pragma unroll
            for (int q = 0; q < 4; q++) acc[mi][ni][q] = 0.f;

    constexpr int nkt = K >> 5;
    load_stage(0, 0);
    load_stage(1, 1);

    int scur = 0, snxt = 2;
    for (int kt = 0; kt < nkt; kt++) {
        if (kt + 1 < nkt) asm volatile("cp.async.wait_group 1;" ::: "memory");
        else              asm volatile("cp.async.wait_group 0;" ::: "memory");
        __syncthreads();
        if (kt + 2 < nkt) {
            load_stage(snxt, kt + 2);
            snxt = (snxt == 2) ? 0 : snxt + 1;
        }

        const uint32_t st = sb + scur * STG;
        scur = (scur == 2) ? 0 : scur + 1;
#pragma unroll
        for (int kk = 0; kk < 2; kk++) {
            uint32_t ah[2][4];
#pragma unroll
            for (int mi = 0; mi < 2; mi++)
                ldm4(st + offA + mi * (16 * RSTRIDE) + kk * 32, ah[mi]);
#pragma unroll
            for (int half = 0; half < 2; half++) {
                uint32_t bf[2][4];
#pragma unroll
                for (int n2 = 0; n2 < 2; n2++)
                    ldm4(st + MTILE_B + offB + (half * 2 + n2) * (16 * RSTRIDE) + kk * 32,
                         bf[n2]);
#pragma unroll
                for (int mi = 0; mi < 2; mi++)
#pragma unroll
                    for (int n2 = 0; n2 < 2; n2++) {
                        const int nf = half * 2 + n2;
                        mma16816(acc[mi][nf * 2 + 0], ah[mi], bf[n2][0], bf[n2][1]);
                        mma16816(acc[mi][nf * 2 + 1], ah[mi], bf[n2][2], bf[n2][3]);
                    }
            }
        }
    }

    // ---- epilogue ----
    const int r0 = m0 + wy * 32 + (lane >> 2);
    const int cbase = n0 + wx * 64 + (lane & 3) * 2;
    float s = 0.f, ss = 0.f;
#pragma unroll
    for (int mi = 0; mi < 2; mi++) {
#pragma unroll
        for (int ni = 0; ni < 8; ni++) {
            const int col = cbase + ni * 8;
            const int ra = r0 + mi * 16;
            const int rb = ra + 8;
            float* c = acc[mi][ni];
            if (EPI == 0) {
                *(float2*)&Dout[(size_t)ra * N + col] = make_float2(c[0], c[1]);
                *(float2*)&Dout[(size_t)rb * N + col] = make_float2(c[2], c[3]);
            } else if (EPI == 1) {
                const float2 bq = *(const float2*)&bias[col];
                ushort2 h0, h1;
                h0.x = __half_as_ushort(__float2half(fmaxf(c[0] + bq.x, 0.f)));
                h0.y = __half_as_ushort(__float2half(fmaxf(c[1] + bq.y, 0.f)));
                h1.x = __half_as_ushort(__float2half(fmaxf(c[2] + bq.x, 0.f)));
                h1.y = __half_as_ushort(__float2half(fmaxf(c[3] + bq.y, 0.f)));
                *(ushort2*)&Z[(size_t)ra * N + col] = h0;
                *(ushort2*)&Z[(size_t)rb * N + col] = h1;
            } else if (EPI == 2) {
                const float2 bq = *(const float2*)&bias[col];
                const float2 q0 = *(const float2*)&res[(size_t)ra * N + col];
                const float2 q1 = *(const float2*)&res[(size_t)rb * N + col];
                *(float2*)&Dout[(size_t)ra * N + col] =
                    make_float2(c[0] + bq.x + q0.x, c[1] + bq.y + q0.y);
                *(float2*)&Dout[(size_t)rb * N + col] =
                    make_float2(c[2] + bq.x + q1.x, c[3] + bq.y + q1.y);
            } else {
                ushort2 h0, h1;
                h0.x = __half_as_ushort(__float2half(c[0]));
                h0.y = __half_as_ushort(__float2half(c[1]));
                h1.x = __half_as_ushort(__float2half(c[2]));
                h1.y = __half_as_ushort(__float2half(c[3]));
                *(ushort2*)&Z[(size_t)ra * N + col] = h0;
                *(ushort2*)&Z[(size_t)rb * N + col] = h1;
                s  += (c[0] + c[1]) + (c[2] + c[3]);
                ss += c[0] * c[0] + c[1] * c[1] + c[2] * c[2] + c[3] * c[3];
            }
        }
    }
    if (EPI == 3) {
        // all lanes of a warp belong to the same batch (wy in {0,1} -> b0, {2,3} -> b1)
#pragma unroll
        for (int o = 16; o > 0; o >>= 1) {
            s  += __shfl_xor_sync(0xFFFFFFFFu, s,  o);
            ss += __shfl_xor_sync(0xFFFFFFFFu, ss, o);
        }
        if (lane == 0) {
            const int b = (m0 >> 6) + (wy >> 1);
            atomicAdd(&ysum[b],   s);
            atomicAdd(&ysumsq[b], ss);
        }
    }
}

// ---------------- launcher ----------------
extern "C" void kernel_launch(void* const* d_in, const int* in_sizes, int n_in,
                              void* d_out, int out_size) {
    const float* x    = (const float*)d_in[0];
    const float* w    = (const float*)d_in[1];
    const float* ln1w = (const float*)d_in[2];
    const float* ln1b = (const float*)d_in[3];
    const float* ln2w = (const float*)d_in[4];
    const float* ln2b = (const float*)d_in[5];
    const float* w1   = (const float*)d_in[6];
    const float* b1   = (const float*)d_in[7];
    const float* w2   = (const float*)d_in[8];
    const float* b2   = (const float*)d_in[9];
    float* out = (float*)d_out;

    float *mu1, *rstd1, *mu2, *rstd2, *ysum, *ysumsq;
    __half *yh, *a1, *a2, *ct, *w1t, *w2t, *z;
    cudaGetSymbolAddress((void**)&mu1,    g_mu1);
    cudaGetSymbolAddress((void**)&rstd1,  g_rstd1);
    cudaGetSymbolAddress((void**)&mu2,    g_mu2);
    cudaGetSymbolAddress((void**)&rstd2,  g_rstd2);
    cudaGetSymbolAddress((void**)&ysum,   g_ysum);
    cudaGetSymbolAddress((void**)&ysumsq, g_ysumsq);
    cudaGetSymbolAddress((void**)&yh,     g_yh);
    cudaGetSymbolAddress((void**)&a1,     g_a1);
    cudaGetSymbolAddress((void**)&a2,     g_a2);
    cudaGetSymbolAddress((void**)&ct,     g_ct);
    cudaGetSymbolAddress((void**)&w1t,    g_w1t);
    cudaGetSymbolAddress((void**)&w2t,    g_w2t);
    cudaGetSymbolAddress((void**)&z,      g_z);

    cudaFuncSetAttribute(hmma_gemm<3, Lc, Lc>, cudaFuncAttributeMaxDynamicSharedMemorySize, DSMEM);
    cudaFuncSetAttribute(hmma_gemm<1, Lc, Hc>, cudaFuncAttributeMaxDynamicSharedMemorySize, DSMEM);
    cudaFuncSetAttribute(hmma_gemm<2, Hc, Lc>, cudaFuncAttributeMaxDynamicSharedMemorySize, DSMEM);

    // 1) LN1 stats + fp16, zero y accumulators
    batch_stats<<<Bb, 256>>>(x, mu1, rstd1);
    zero_acc<<<2, 256>>>(ysum, ysumsq);
    ln_fp16<<<(Mc * Lc / 4) / 256, 256>>>(x, mu1, rstd1, ln1w, ln1b, a1);
    // 2) operand prep (fp16)
    build_ct<<<dim3(2, Lc), 256>>>(w, ct);
    transpose_h<<<dim3(Hc / 32, Lc / 32), dim3(32, 8)>>>(w1, w1t, Lc, Hc);
    transpose_h<<<dim3(Lc / 32, Hc / 32), dim3(32, 8)>>>(w2, w2t, Hc, Lc);
    // 3) y = LN1(x) @ C  (fp16 out + fused stats)   M=32768 K=512 N=512
    hmma_gemm<3, Lc, Lc><<<dim3(Lc / 128, Mc / 128), 256, DSMEM>>>(
        a1, ct, nullptr, yh, nullptr, nullptr, ysum, ysumsq);
    // 4) finalize stats + LN2 -> fp16
    finalize_stats<<<2, 256>>>(ysum, ysumsq, mu2, rstd2);
    ln_fp16_h<<<(Mc * Lc / 4) / 256, 256>>>(yh, mu2, rstd2, ln2w, ln2b, a2);
    // 5) z = fp16(relu(LN2(y) @ w1 + b1))   M=32768 K=512 N=2048
    hmma_gemm<1, Lc, Hc><<<dim3(Hc / 128, Mc / 128), 256, DSMEM>>>(
        a2, w1t, nullptr, z, b1, nullptr, nullptr, nullptr);
    // 6) out = z @ w2 + b2 + x              M=32768 K=2048 N=512
    hmma_gemm<2, Hc, Lc><<<dim3(Lc / 128, Mc / 128), 256, DSMEM>>>(
        z, w2t, out, nullptr, b2, x, nullptr, nullptr);
}

// round 8
// speedup vs baseline: 6.6596x; 1.0324x over previous
#include <cuda_runtime.h>
#include <cuda_fp16.h>
#include <math.h>
#include <stdint.h>

#define Bb  512
#define P1c 64
#define Lc  512
#define Hc  2048
#define Mc  (Bb * P1c)   // 32768 rows

// ---------------- scratch ----------------
__device__ float g_mu1[Bb];
__device__ float g_rstd1[Bb];
__device__ float g_mu2[Bb];
__device__ float g_rstd2[Bb];
__device__ float g_ysum[Bb];
__device__ float g_ysumsq[Bb];
__device__ __half g_yh[(size_t)Mc * Lc];               // filtered y fp16, 32 MB
__device__ __half g_a1[(size_t)Mc * Lc];               // LN1(x) fp16
__device__ __half g_a2[(size_t)Mc * Lc];               // LN2(y) fp16
__device__ __half g_ct[Lc * Lc];                       // C^T [N,K] fp16
__device__ __half g_w1t[(size_t)Hc * Lc];              // w1^T [2048,512] fp16
__device__ __half g_w2t[(size_t)Lc * Hc];              // w2^T [512,2048] fp16
__device__ __half g_z[(size_t)Mc * Hc];                // FFN hidden fp16, 128 MB

// ---------------- helpers ----------------
__device__ __forceinline__ uint32_t smem_u32(const void* p) {
    uint32_t a;
    asm("{ .reg .u64 t; cvta.to.shared.u64 t, %1; cvt.u32.u64 %0, t; }" : "=r"(a) : "l"(p));
    return a;
}
__device__ __forceinline__ void cp16(uint32_t dst, const void* src) {
    asm volatile("cp.async.cg.shared.global [%0], [%1], 16;"
                 :: "r"(dst), "l"((unsigned long long)__cvta_generic_to_global(src)));
}
__device__ __forceinline__ void ldm4(uint32_t addr, uint32_t* r) {
    asm volatile("ldmatrix.sync.aligned.m8n8.x4.shared.b16 {%0,%1,%2,%3}, [%4];"
                 : "=r"(r[0]), "=r"(r[1]), "=r"(r[2]), "=r"(r[3]) : "r"(addr));
}
__device__ __forceinline__ void mma16816(float* c, const uint32_t* a,
                                         uint32_t b0, uint32_t b1) {
    asm volatile(
        "mma.sync.aligned.m16n8k16.row.col.f32.f16.f16.f32 "
        "{%0,%1,%2,%3}, {%4,%5,%6,%7}, {%8,%9}, {%0,%1,%2,%3};"
        : "+f"(c[0]), "+f"(c[1]), "+f"(c[2]), "+f"(c[3])
        : "r"(a[0]), "r"(a[1]), "r"(a[2]), "r"(a[3]), "r"(b0), "r"(b1));
}

// ---------------- per-batch mean / rstd over (P1, L) fp32 input ----------------
__global__ void batch_stats(const float* __restrict__ x,
                            float* __restrict__ mu, float* __restrict__ rstd) {
    const int NPER = P1c * Lc;
    const int b = blockIdx.x;
    const float4* xb = reinterpret_cast<const float4*>(x) + (size_t)b * (NPER / 4);
    float s = 0.f, ss = 0.f;
    for (int i = threadIdx.x; i < NPER / 4; i += blockDim.x) {
        float4 v = xb[i];
        s  += (v.x + v.y) + (v.z + v.w);
        ss += v.x * v.x + v.y * v.y + v.z * v.z + v.w * v.w;
    }
    __shared__ float sh_s[32], sh_ss[32];
    const int lane = threadIdx.x & 31, wid = threadIdx.x >> 5;
    for (int o = 16; o > 0; o >>= 1) {
        s  += __shfl_xor_sync(0xFFFFFFFFu, s,  o);
        ss += __shfl_xor_sync(0xFFFFFFFFu, ss, o);
    }
    if (lane == 0) { sh_s[wid] = s; sh_ss[wid] = ss; }
    __syncthreads();
    if (wid == 0) {
        const int nw = blockDim.x >> 5;
        s  = (lane < nw) ? sh_s[lane]  : 0.f;
        ss = (lane < nw) ? sh_ss[lane] : 0.f;
        for (int o = 16; o > 0; o >>= 1) {
            s  += __shfl_xor_sync(0xFFFFFFFFu, s,  o);
            ss += __shfl_xor_sync(0xFFFFFFFFu, ss, o);
        }
        if (lane == 0) {
            float m = s / NPER;
            float var = ss / NPER - m * m;
            mu[b] = m;
            rstd[b] = rsqrtf(var + 1e-5f);
        }
    }
}

// ---------------- zero per-batch accumulators ----------------
__global__ void zero_acc(float* __restrict__ s, float* __restrict__ ss) {
    int i = threadIdx.x + blockIdx.x * blockDim.x;
    if (i < Bb) { s[i] = 0.f; ss[i] = 0.f; }
}

// ---------------- finalize y stats ----------------
__global__ void finalize_stats(const float* __restrict__ s, const float* __restrict__ ss,
                               float* __restrict__ mu, float* __restrict__ rstd) {
    int i = threadIdx.x + blockIdx.x * blockDim.x;
    if (i < Bb) {
        const float inv = 1.f / (P1c * Lc);
        float m = s[i] * inv;
        float var = ss[i] * inv - m * m;
        mu[i] = m;
        rstd[i] = rsqrtf(var + 1e-5f);
    }
}

// ---------------- LN(fp32 in) -> fp16 ----------------
__global__ void ln_fp16(const float* __restrict__ x,
                        const float* __restrict__ mu, const float* __restrict__ rstd,
                        const float* __restrict__ g, const float* __restrict__ bb,
                        __half* __restrict__ out) {
    size_t idx = (size_t)blockIdx.x * blockDim.x + threadIdx.x;
    int row = (int)(idx >> 7);
    int c4  = (int)(idx & 127) << 2;
    int b = row >> 6, p = row & 63;
    float m = mu[b], r = rstd[b];
    float4 v  = *(const float4*)&x[(size_t)row * Lc + c4];
    float4 gv = *(const float4*)&g[p * Lc + c4];
    float4 bv = *(const float4*)&bb[p * Lc + c4];
    ushort4 h4;
    h4.x = __half_as_ushort(__float2half((v.x - m) * r * gv.x + bv.x));
    h4.y = __half_as_ushort(__float2half((v.y - m) * r * gv.y + bv.y));
    h4.z = __half_as_ushort(__float2half((v.z - m) * r * gv.z + bv.z));
    h4.w = __half_as_ushort(__float2half((v.w - m) * r * gv.w + bv.w));
    *(ushort4*)&out[(size_t)row * Lc + c4] = h4;
}

// ---------------- LN(fp16 in) -> fp16 ----------------
__global__ void ln_fp16_h(const __half* __restrict__ x,
                          const float* __restrict__ mu, const float* __restrict__ rstd,
                          const float* __restrict__ g, const float* __restrict__ bb,
                          __half* __restrict__ out) {
    size_t idx = (size_t)blockIdx.x * blockDim.x + threadIdx.x;
    int row = (int)(idx >> 7);
    int c4  = (int)(idx & 127) << 2;
    int b = row >> 6, p = row & 63;
    float m = mu[b], r = rstd[b];
    ushort4 xv = *(const ushort4*)&x[(size_t)row * Lc + c4];
    float4 gv = *(const float4*)&g[p * Lc + c4];
    float4 bv = *(const float4*)&bb[p * Lc + c4];
    ushort4 h4;
    h4.x = __half_as_ushort(__float2half((__half2float(__ushort_as_half(xv.x)) - m) * r * gv.x + bv.x));
    h4.y = __half_as_ushort(__float2half((__half2float(__ushort_as_half(xv.y)) - m) * r * gv.y + bv.y));
    h4.z = __half_as_ushort(__float2half((__half2float(__ushort_as_half(xv.z)) - m) * r * gv.z + bv.z));
    h4.w = __half_as_ushort(__float2half((__half2float(__ushort_as_half(xv.w)) - m) * r * gv.w + bv.w));
    *(ushort4*)&out[(size_t)row * Lc + c4] = h4;
}

// ---------------- Ct[n][k] = w[(n-k)&511]/sqrt(L), fp16 ----------------
__global__ void build_ct(const float* __restrict__ w, __half* __restrict__ ct) {
    int k = blockIdx.x * blockDim.x + threadIdx.x;
    int n = blockIdx.y;
    ct[n * Lc + k] = __float2half(w[(n - k) & (Lc - 1)] * 0.04419417382415922f);
}

// ---------------- transpose -> fp16: [K,N] fp32 -> [N,K] ----------------
__global__ void transpose_h(const float* __restrict__ in, __half* __restrict__ outp,
                            int K, int N) {
    __shared__ float t[32][33];
    int n0 = blockIdx.x * 32, k0 = blockIdx.y * 32;
    int tx = threadIdx.x, ty = threadIdx.y;
    for (int i = ty; i < 32; i += 8)
        t[i][tx] = in[(size_t)(k0 + i) * N + n0 + tx];
    __syncthreads();
    for (int i = ty; i < 32; i += 8)
        outp[(size_t)(n0 + i) * K + k0 + tx] = __float2half(t[tx][i]);
}

// ---------------- HMMA fp16 GEMM ----------------
// CTA tile 128x128, BK=32, 4 warps (2M x 2N), warp tile 64x64 (square ->
// minimal LDSM bytes/MAC). 3-stage cp.async pipeline, 2 CTAs/SM, one sync/kt.
// EPI 0: Dout=acc
// EPI 1: Z = fp16(relu(acc+bias))
// EPI 2: Dout=acc+bias+res
// EPI 3: Z = fp16(acc), plus per-batch sum/sumsq atomics (ysum/ysumsq)
#define RSTRIDE 80                      // 64B data + 16B pad per k-row
#define MTILE_B (128 * RSTRIDE)         // 10240 per matrix
#define STG     (2 * MTILE_B)           // A, B = 20480
#define DSMEM   (3 * STG)               // 61440

template <int EPI, int K, int N>
__global__ void __launch_bounds__(128, 2)
hmma_gemm(const __half* __restrict__ A, const __half* __restrict__ B,
          float* __restrict__ Dout, __half* __restrict__ Z,
          const float* __restrict__ bias, const float* __restrict__ res,
          float* __restrict__ ysum, float* __restrict__ ysumsq) {
    extern __shared__ char smem[];
    const uint32_t sb = smem_u32(smem);
    const int tid = threadIdx.x, wid = tid >> 5, lane = tid & 31;
    const int wy = wid & 1, wx = wid >> 1;            // 2 M-warps x 2 N-warps
    const int m0 = blockIdx.y * 128, n0 = blockIdx.x * 128;

    const uint32_t offA = (uint32_t)((wy * 64 + (lane & 7) + ((lane >> 3) & 1) * 8) * RSTRIDE
                                     + (lane >> 4) * 16);
    const uint32_t offB = (uint32_t)((wx * 64 + (lane & 7) + (lane >> 4) * 8) * RSTRIDE
                                     + ((lane >> 3) & 1) * 16);

    auto load_stage = [&](int s, int kt) {
        const uint32_t ab = sb + s * STG;
#pragma unroll
        for (int i = 0; i < 4; i++) {
            const int j = tid + (i << 7);       // 0..511
            const int row = j >> 2, c = j & 3;
            const uint32_t off = row * RSTRIDE + c * 16;
            const size_t asrc = (size_t)(m0 + row) * K + (size_t)kt * 32 + c * 8;
            const size_t bsrc = (size_t)(n0 + row) * K + (size_t)kt * 32 + c * 8;
            cp16(ab + off,           A + asrc);
            cp16(ab + MTILE_B + off, B + bsrc);
        }
        asm volatile("cp.async.commit_group;");
    };

    float acc[4][8][4];
#pragma unroll
    for (int mi = 0; mi < 4; mi++)
#pragma unroll
        for (int ni = 0; ni < 8; ni++)
#pragma unroll
            for (int q = 0; q < 4; q++) acc[mi][ni][q] = 0.f;

    constexpr int nkt = K >> 5;
    load_stage(0, 0);
    load_stage(1, 1);

    int scur = 0, snxt = 2;
    for (int kt = 0; kt < nkt; kt++) {
        if (kt + 1 < nkt) asm volatile("cp.async.wait_group 1;" ::: "memory");
        else              asm volatile("cp.async.wait_group 0;" ::: "memory");
        __syncthreads();
        if (kt + 2 < nkt) {
            load_stage(snxt, kt + 2);
            snxt = (snxt == 2) ? 0 : snxt + 1;
        }

        const uint32_t st = sb + scur * STG;
        scur = (scur == 2) ? 0 : scur + 1;
#pragma unroll
        for (int kk = 0; kk < 2; kk++) {
            uint32_t ah[4][4], bf[4][4];
#pragma unroll
            for (int mi = 0; mi < 4; mi++)
                ldm4(st + offA + mi * (16 * RSTRIDE) + kk * 32, ah[mi]);
#pragma unroll
            for (int nf = 0; nf < 4; nf++)
                ldm4(st + MTILE_B + offB + nf * (16 * RSTRIDE) + kk * 32, bf[nf]);
#pragma unroll
            for (int mi = 0; mi < 4; mi++)
#pragma unroll
                for (int nf = 0; nf < 4; nf++) {
                    mma16816(acc[mi][nf * 2 + 0], ah[mi], bf[nf][0], bf[nf][1]);
                    mma16816(acc[mi][nf * 2 + 1], ah[mi], bf[nf][2], bf[nf][3]);
                }
        }
    }

    // ---- epilogue ----
    const int r0 = m0 + wy * 64 + (lane >> 2);
    const int cbase = n0 + wx * 64 + (lane & 3) * 2;
    float s = 0.f, ss = 0.f;
#pragma unroll
    for (int mi = 0; mi < 4; mi++) {
#pragma unroll
        for (int ni = 0; ni < 8; ni++) {
            const int col = cbase + ni * 8;
            const int ra = r0 + mi * 16;
            const int rb = ra + 8;
            float* c = acc[mi][ni];
            if (EPI == 0) {
                *(float2*)&Dout[(size_t)ra * N + col] = make_float2(c[0], c[1]);
                *(float2*)&Dout[(size_t)rb * N + col] = make_float2(c[2], c[3]);
            } else if (EPI == 1) {
                const float2 bq = *(const float2*)&bias[col];
                ushort2 h0, h1;
                h0.x = __half_as_ushort(__float2half(fmaxf(c[0] + bq.x, 0.f)));
                h0.y = __half_as_ushort(__float2half(fmaxf(c[1] + bq.y, 0.f)));
                h1.x = __half_as_ushort(__float2half(fmaxf(c[2] + bq.x, 0.f)));
                h1.y = __half_as_ushort(__float2half(fmaxf(c[3] + bq.y, 0.f)));
                *(ushort2*)&Z[(size_t)ra * N + col] = h0;
                *(ushort2*)&Z[(size_t)rb * N + col] = h1;
            } else if (EPI == 2) {
                const float2 bq = *(const float2*)&bias[col];
                const float2 q0 = *(const float2*)&res[(size_t)ra * N + col];
                const float2 q1 = *(const float2*)&res[(size_t)rb * N + col];
                *(float2*)&Dout[(size_t)ra * N + col] =
                    make_float2(c[0] + bq.x + q0.x, c[1] + bq.y + q0.y);
                *(float2*)&Dout[(size_t)rb * N + col] =
                    make_float2(c[2] + bq.x + q1.x, c[3] + bq.y + q1.y);
            } else {
                ushort2 h0, h1;
                h0.x = __half_as_ushort(__float2half(c[0]));
                h0.y = __half_as_ushort(__float2half(c[1]));
                h1.x = __half_as_ushort(__float2half(c[2]));
                h1.y = __half_as_ushort(__float2half(c[3]));
                *(ushort2*)&Z[(size_t)ra * N + col] = h0;
                *(ushort2*)&Z[(size_t)rb * N + col] = h1;
                s  += (c[0] + c[1]) + (c[2] + c[3]);
                ss += c[0] * c[0] + c[1] * c[1] + c[2] * c[2] + c[3] * c[3];
            }
        }
    }
    if (EPI == 3) {
        // warp rows m0 + wy*64 .. +63 lie in exactly one 64-row batch
#pragma unroll
        for (int o = 16; o > 0; o >>= 1) {
            s  += __shfl_xor_sync(0xFFFFFFFFu, s,  o);
            ss += __shfl_xor_sync(0xFFFFFFFFu, ss, o);
        }
        if (lane == 0) {
            const int b = (m0 >> 6) + wy;
            atomicAdd(&ysum[b],   s);
            atomicAdd(&ysumsq[b], ss);
        }
    }
}

// ---------------- launcher ----------------
extern "C" void kernel_launch(void* const* d_in, const int* in_sizes, int n_in,
                              void* d_out, int out_size) {
    const float* x    = (const float*)d_in[0];
    const float* w    = (const float*)d_in[1];
    const float* ln1w = (const float*)d_in[2];
    const float* ln1b = (const float*)d_in[3];
    const float* ln2w = (const float*)d_in[4];
    const float* ln2b = (const float*)d_in[5];
    const float* w1   = (const float*)d_in[6];
    const float* b1   = (const float*)d_in[7];
    const float* w2   = (const float*)d_in[8];
    const float* b2   = (const float*)d_in[9];
    float* out = (float*)d_out;

    float *mu1, *rstd1, *mu2, *rstd2, *ysum, *ysumsq;
    __half *yh, *a1, *a2, *ct, *w1t, *w2t, *z;
    cudaGetSymbolAddress((void**)&mu1,    g_mu1);
    cudaGetSymbolAddress((void**)&rstd1,  g_rstd1);
    cudaGetSymbolAddress((void**)&mu2,    g_mu2);
    cudaGetSymbolAddress((void**)&rstd2,  g_rstd2);
    cudaGetSymbolAddress((void**)&ysum,   g_ysum);
    cudaGetSymbolAddress((void**)&ysumsq, g_ysumsq);
    cudaGetSymbolAddress((void**)&yh,     g_yh);
    cudaGetSymbolAddress((void**)&a1,     g_a1);
    cudaGetSymbolAddress((void**)&a2,     g_a2);
    cudaGetSymbolAddress((void**)&ct,     g_ct);
    cudaGetSymbolAddress((void**)&w1t,    g_w1t);
    cudaGetSymbolAddress((void**)&w2t,    g_w2t);
    cudaGetSymbolAddress((void**)&z,      g_z);

    cudaFuncSetAttribute(hmma_gemm<3, Lc, Lc>, cudaFuncAttributeMaxDynamicSharedMemorySize, DSMEM);
    cudaFuncSetAttribute(hmma_gemm<1, Lc, Hc>, cudaFuncAttributeMaxDynamicSharedMemorySize, DSMEM);
    cudaFuncSetAttribute(hmma_gemm<2, Hc, Lc>, cudaFuncAttributeMaxDynamicSharedMemorySize, DSMEM);

    // 1) LN1 stats + fp16, zero y accumulators
    batch_stats<<<Bb, 256>>>(x, mu1, rstd1);
    zero_acc<<<2, 256>>>(ysum, ysumsq);
    ln_fp16<<<(Mc * Lc / 4) / 256, 256>>>(x, mu1, rstd1, ln1w, ln1b, a1);
    // 2) operand prep (fp16)
    build_ct<<<dim3(2, Lc), 256>>>(w, ct);
    transpose_h<<<dim3(Hc / 32, Lc / 32), dim3(32, 8)>>>(w1, w1t, Lc, Hc);
    transpose_h<<<dim3(Lc / 32, Hc / 32), dim3(32, 8)>>>(w2, w2t, Hc, Lc);
    // 3) y = LN1(x) @ C  (fp16 out + fused stats)   M=32768 K=512 N=512
    hmma_gemm<3, Lc, Lc><<<dim3(Lc / 128, Mc / 128), 128, DSMEM>>>(
        a1, ct, nullptr, yh, nullptr, nullptr, ysum, ysumsq);
    // 4) finalize stats + LN2 -> fp16
    finalize_stats<<<2, 256>>>(ysum, ysumsq, mu2, rstd2);
    ln_fp16_h<<<(Mc * Lc / 4) / 256, 256>>>(yh, mu2, rstd2, ln2w, ln2b, a2);
    // 5) z = fp16(relu(LN2(y) @ w1 + b1))   M=32768 K=512 N=2048
    hmma_gemm<1, Lc, Hc><<<dim3(Hc / 128, Mc / 128), 128, DSMEM>>>(
        a2, w1t, nullptr, z, b1, nullptr, nullptr, nullptr);
    // 6) out = z @ w2 + b2 + x              M=32768 K=2048 N=512
    hmma_gemm<2, Hc, Lc><<<dim3(Lc / 128, Mc / 128), 128, DSMEM>>>(
        z, w2t, out, nullptr, b2, x, nullptr, nullptr);
}